// round 5
// baseline (speedup 1.0000x reference)
#include <cuda_runtime.h>
#include <math.h>

#define TC   4096
#define TQ   128
#define DHID 356
#define DD2  712
#define NGT  1424
#define QACD 2848
#define UPB  8
#define NB   45      // ceil(356/8) blocks per direction

// ---------------- scratch (device globals; no allocation allowed) ----------------
__device__ float d_wt[5*100*100];
__device__ float d_x_ctx[TC*DHID];
__device__ float d_x_qry[TQ*DHID];
__device__ float d_t1[TC*DHID];
__device__ float d_t2[TC*DHID];
__device__ float d_xWf[TC*NGT];
__device__ float d_xWb[TC*NGT];
__device__ float d_Cb[TC*DD2];
__device__ float d_Qb[TQ*DD2];
__device__ float d_Qt[DD2*TQ];
__device__ float d_CW[TC*DD2];
__device__ float d_sim[TC*TQ];
__device__ float d_cw[TC];
__device__ float d_qw[TQ];
__device__ float d_rowmax[TC];
__device__ float d_alpha[TC];
__device__ float d_c2q[TC*DD2];
__device__ float d_q2c[DD2];
__device__ float d_qac[TC*QACD];
__device__ float d_Mb[TC*DD2];
__device__ float d_M2b[TC*DD2];
__device__ float d_lg[TC];
__device__ float g_hbuf[2][2][DHID];   // [dir][step parity][unit]
__device__ int   g_flags[2][64];       // [dir][block]

// ---------------- conv weight transpose: w[o][i][k] -> wt[k][i][o] ----------------
__global__ void k_convw(const float* __restrict__ w) {
    int idx = blockIdx.x*256 + threadIdx.x;
    if (idx < 50000) {
        int o = idx / 500; int r = idx - o*500; int i = r/5; int k = r - i*5;
        d_wt[(k*100+i)*100 + o] = w[idx];
    }
}

// ---------------- char CNN: one block per token ----------------
__global__ void k_charcnn(const int* __restrict__ chars, const float* __restrict__ emb,
                          const float* __restrict__ cb, float* __restrict__ xo)
{
    __shared__ float es[20][100];
    int t = blockIdx.x, tid = threadIdx.x;
    for (int idx = tid; idx < 2000; idx += 128) ((float*)es)[idx] = 0.f;
    __syncthreads();
    for (int idx = tid; idx < 1600; idx += 128) {
        int h = idx / 100, c = idx - h*100;
        es[h+2][c] = emb[chars[t*16+h]*100 + c];
    }
    __syncthreads();
    if (tid < 100) {
        float acc[16];
        float b = cb[tid];
        #pragma unroll
        for (int h = 0; h < 16; ++h) acc[h] = b;
        for (int i = 0; i < 100; ++i) {
            float ev[20];
            #pragma unroll
            for (int h2 = 0; h2 < 20; ++h2) ev[h2] = es[h2][i];
            #pragma unroll
            for (int k = 0; k < 5; ++k) {
                float wv = d_wt[(k*100+i)*100 + tid];
                #pragma unroll
                for (int h = 0; h < 16; ++h) acc[h] += ev[h+k]*wv;
            }
        }
        float m = acc[0];
        #pragma unroll
        for (int h = 1; h < 16; ++h) m = fmaxf(m, acc[h]);
        xo[t*DHID + tid] = m;
    }
}

// ---------------- elmo concat copy ----------------
__global__ void k_elmo(const float* __restrict__ e, float* __restrict__ xo, int T) {
    int idx = blockIdx.x*256 + threadIdx.x;
    if (idx < T*256) { int t = idx >> 8, j = idx & 255; xo[t*DHID + 100 + j] = e[idx]; }
}

// ---------------- SGEMM: C = A(MxK) * B(NxK)^T (+ bias[n]) ----------------
__global__ __launch_bounds__(256)
void k_gemm_abt(const float* __restrict__ A, const float* __restrict__ B,
                const float* __restrict__ bias, float* __restrict__ C,
                int M, int N, int K)
{
    __shared__ float As[8][132];
    __shared__ float Bs[8][132];
    int bm = blockIdx.y*128, bn = blockIdx.x*128;
    int tid = threadIdx.x;
    int tx = tid & 15, ty = tid >> 4;
    int lrow = tid >> 1;
    int lk4  = (tid & 1)*4;
    float acc[8][8];
    #pragma unroll
    for (int i = 0; i < 8; ++i)
        #pragma unroll
        for (int j = 0; j < 8; ++j) acc[i][j] = 0.f;
    int ar = bm + lrow;
    int br = bn + lrow;
    for (int kt = 0; kt < K; kt += 8) {
        float4 av = make_float4(0.f,0.f,0.f,0.f);
        float4 bv = make_float4(0.f,0.f,0.f,0.f);
        int ak = kt + lk4;
        if (ar < M && ak < K) av = *reinterpret_cast<const float4*>(A + (size_t)ar*K + ak);
        if (br < N && ak < K) bv = *reinterpret_cast<const float4*>(B + (size_t)br*K + ak);
        __syncthreads();
        As[lk4+0][lrow]=av.x; As[lk4+1][lrow]=av.y; As[lk4+2][lrow]=av.z; As[lk4+3][lrow]=av.w;
        Bs[lk4+0][lrow]=bv.x; Bs[lk4+1][lrow]=bv.y; Bs[lk4+2][lrow]=bv.z; Bs[lk4+3][lrow]=bv.w;
        __syncthreads();
        #pragma unroll
        for (int k = 0; k < 8; ++k) {
            float4 a0 = *reinterpret_cast<const float4*>(&As[k][ty*8]);
            float4 a1 = *reinterpret_cast<const float4*>(&As[k][ty*8+4]);
            float4 b0 = *reinterpret_cast<const float4*>(&Bs[k][tx*8]);
            float4 b1 = *reinterpret_cast<const float4*>(&Bs[k][tx*8+4]);
            float a[8] = {a0.x,a0.y,a0.z,a0.w,a1.x,a1.y,a1.z,a1.w};
            float b[8] = {b0.x,b0.y,b0.z,b0.w,b1.x,b1.y,b1.z,b1.w};
            #pragma unroll
            for (int i = 0; i < 8; ++i)
                #pragma unroll
                for (int j = 0; j < 8; ++j) acc[i][j] += a[i]*b[j];
        }
    }
    #pragma unroll
    for (int i = 0; i < 8; ++i) {
        int row = bm + ty*8 + i;
        if (row >= M) continue;
        #pragma unroll
        for (int j = 0; j < 8; ++j) {
            int col = bn + tx*8 + j;
            if (col < N) {
                float v = acc[i][j];
                if (bias) v += bias[col];
                C[(size_t)row*N + col] = v;
            }
        }
    }
}

// ---------------- highway combine ----------------
__global__ void k_hwy(float* __restrict__ x, const float* __restrict__ g,
                      const float* __restrict__ p, int n)
{
    int i = blockIdx.x*256 + threadIdx.x;
    if (i < n) {
        float gv = 1.f/(1.f + expf(-g[i]));
        float pv = fmaxf(p[i], 0.f);
        x[i] = gv*pv + (1.f - gv)*x[i];
    }
}

// ---------------- flag reset before each scan ----------------
__global__ void k_zeroflags() {
    int i = threadIdx.x;
    if (i < 128) ((int*)g_flags)[i] = 0;
}

// ---------------- persistent BiLSTM scan (both directions in one launch) ----------
// 45 blocks/direction, 8 units/block, 1024 threads (32 warps = 32 gate rows).
// Flag-array barrier (no contended atomics), double-buffered h by step parity,
// xW prefetch overlapped with the barrier wait.
__global__ __launch_bounds__(1024, 1)
void k_scan(const float* __restrict__ xWf, const float* __restrict__ xWb,
            const float* __restrict__ Whh, const float* __restrict__ h0,
            float* __restrict__ out, int T)
{
    __shared__ float ws[32][DHID];
    __shared__ float zred[32];
    __shared__ float cs[UPB];
    int dir = blockIdx.x / NB;
    int blk = blockIdx.x - dir*NB;
    int tid = threadIdx.x;
    int warp = tid >> 5, lane = tid & 31;
    const float* xW = dir ? xWb : xWf;
    const float* W  = Whh + (size_t)dir*NGT*DHID;
    int u0 = blk*UPB;

    int r  = warp;                 // gate row: r = g*8 + ui
    int gg = r >> 3, ui = r & 7;
    int uu_r = u0 + ui;
    int j  = gg*DHID + uu_r;       // row in [0,1424)
    bool rowvalid = (uu_r < DHID);

    // load this block's 32 Whh rows into smem
    for (int idx = tid; idx < 32*DHID; idx += 1024) {
        int rr = idx / DHID, k = idx - rr*DHID;
        int g2 = rr >> 3, u2 = rr & 7;
        ws[rr][k] = (u0+u2 < DHID) ? W[(size_t)(g2*DHID + u0 + u2)*DHID + k] : 0.f;
    }
    // h(t-1) registers (from h0)
    float hreg[12];
    #pragma unroll
    for (int i = 0; i < 11; ++i) hreg[i] = h0[dir*DHID + lane + 32*i];
    hreg[11] = (lane < 4) ? h0[dir*DHID + 352 + lane] : 0.f;
    if (tid < UPB) cs[tid] = (u0+tid < DHID) ? h0[dir*DHID + u0 + tid] : 0.f;

    float xw = 0.f;
    if (lane == 0 && rowvalid) {
        int ti0 = dir ? (T-1) : 0;
        xw = __ldg(&xW[(size_t)ti0*NGT + j]);
    }
    __syncthreads();

    volatile int* flags = &g_flags[dir][0];

    for (int t = 0; t < T; ++t) {
        int ti = dir ? (T-1-t) : t;
        // --- h @ Whh^T for this warp's gate row ---
        float s = 0.f;
        #pragma unroll
        for (int i = 0; i < 11; ++i) s += ws[r][lane + 32*i]*hreg[i];
        if (lane < 4) s += ws[r][352 + lane]*hreg[11];
        #pragma unroll
        for (int o = 16; o; o >>= 1) s += __shfl_down_sync(0xffffffffu, s, o);
        if (lane == 0) zred[r] = s + xw;
        __syncthreads();

        volatile float* hw = &g_hbuf[dir][t & 1][0];
        if (warp == 0) {
            // 32 lanes: one activation each, gather via shfl
            float z = zred[lane];
            float a = ((lane >> 3) == 2) ? tanhf(z)
                                         : __fdividef(1.f, 1.f + __expf(-z));
            int u = lane & 7;
            float si = __shfl_sync(0xffffffffu, a, u);
            float sf = __shfl_sync(0xffffffffu, a, 8 + u);
            float tg = __shfl_sync(0xffffffffu, a, 16 + u);
            float so = __shfl_sync(0xffffffffu, a, 24 + u);
            float h = 0.f;
            int uu = u0 + lane;
            if (lane < UPB) {
                float c = sf*cs[lane] + si*tg;
                h = so*tanhf(c);
                cs[lane] = c;
                if (uu < DHID) hw[uu] = h;
            }
            __threadfence();
            __syncwarp(0xffffffffu);
            if (lane == 0) flags[blk] = t + 1;
            if (lane < UPB && uu < DHID)
                out[(size_t)ti*DD2 + dir*DHID + uu] = h;
        }
        // prefetch next step's xW during barrier wait
        if (lane == 0 && rowvalid && t + 1 < T) {
            int tn = dir ? (T-2-t) : (t+1);
            xw = __ldg(&xW[(size_t)tn*NGT + j]);
        }
        if (t + 1 < T) {
            int tgt = t + 1;
            for (;;) {
                int v0 = (lane       < NB) ? flags[lane]      : tgt;
                int v1 = (lane + 32  < NB) ? flags[lane + 32] : tgt;
                if (__all_sync(0xffffffffu, (v0 >= tgt) && (v1 >= tgt))) break;
            }
            volatile float* hr = &g_hbuf[dir][t & 1][0];
            #pragma unroll
            for (int i = 0; i < 11; ++i) hreg[i] = hr[lane + 32*i];
            if (lane < 4) hreg[11] = hr[352 + lane];
        }
    }
}

// ---------------- row dot (gemv): o[t] = X[t,:K] . w ----------------
__global__ void k_rowdot(const float* __restrict__ X, const float* __restrict__ w,
                         float* __restrict__ o, int T, int K)
{
    int t = blockIdx.x*8 + (threadIdx.x >> 5);
    int lane = threadIdx.x & 31;
    if (t >= T) return;
    float s = 0.f;
    for (int k = lane; k < K; k += 32) s += X[(size_t)t*K + k]*w[k];
    #pragma unroll
    for (int off = 16; off; off >>= 1) s += __shfl_down_sync(0xffffffffu, s, off);
    if (lane == 0) o[t] = s;
}

__global__ void k_scalecols(const float* __restrict__ C, const float* __restrict__ w,
                            float* __restrict__ o, int n)
{
    int i = blockIdx.x*256 + threadIdx.x;
    if (i < n) o[i] = C[i]*w[i % DD2];
}

__global__ void k_qt() {
    int i = blockIdx.x*256 + threadIdx.x;
    if (i < DD2*TQ) { int j = i / TQ, q = i - j*TQ; d_Qt[i] = d_Qb[q*DD2 + j]; }
}

// sim[t][q] += cw[t]+qw[q]; rowmax; row softmax in-place
__global__ void k_simsm() {
    int t = blockIdx.x*8 + (threadIdx.x >> 5);
    int lane = threadIdx.x & 31;
    if (t >= TC) return;
    float cw = d_cw[t];
    float v[4];
    float m = -1e30f;
    #pragma unroll
    for (int i = 0; i < 4; ++i) {
        int q = lane + 32*i;
        v[i] = d_sim[t*TQ + q] + cw + d_qw[q];
        m = fmaxf(m, v[i]);
    }
    #pragma unroll
    for (int off = 16; off; off >>= 1) m = fmaxf(m, __shfl_xor_sync(0xffffffffu, m, off));
    float s = 0.f;
    #pragma unroll
    for (int i = 0; i < 4; ++i) { v[i] = expf(v[i]-m); s += v[i]; }
    #pragma unroll
    for (int off = 16; off; off >>= 1) s += __shfl_xor_sync(0xffffffffu, s, off);
    float inv = 1.f/s;
    #pragma unroll
    for (int i = 0; i < 4; ++i) d_sim[t*TQ + lane + 32*i] = v[i]*inv;
    if (lane == 0) d_rowmax[t] = m;
}

__device__ __forceinline__ float blkMax(float v, float* sh) {
    int lane = threadIdx.x & 31, w = threadIdx.x >> 5;
    #pragma unroll
    for (int o = 16; o; o >>= 1) v = fmaxf(v, __shfl_xor_sync(0xffffffffu, v, o));
    if (lane == 0) sh[w] = v;
    __syncthreads();
    if (w == 0) {
        float x = sh[lane];
        #pragma unroll
        for (int o = 16; o; o >>= 1) x = fmaxf(x, __shfl_xor_sync(0xffffffffu, x, o));
        if (lane == 0) sh[0] = x;
    }
    __syncthreads();
    float r = sh[0];
    __syncthreads();
    return r;
}
__device__ __forceinline__ float blkSum(float v, float* sh) {
    int lane = threadIdx.x & 31, w = threadIdx.x >> 5;
    #pragma unroll
    for (int o = 16; o; o >>= 1) v += __shfl_xor_sync(0xffffffffu, v, o);
    if (lane == 0) sh[w] = v;
    __syncthreads();
    if (w == 0) {
        float x = sh[lane];
        #pragma unroll
        for (int o = 16; o; o >>= 1) x += __shfl_xor_sync(0xffffffffu, x, o);
        if (lane == 0) sh[0] = x;
    }
    __syncthreads();
    float r = sh[0];
    __syncthreads();
    return r;
}

// softmax over rowmax (4096) -> alpha; also zero q2c
__global__ void k_alphasm() {
    __shared__ float sh[32];
    int tid = threadIdx.x;
    float m = -1e30f;
    for (int i = tid; i < TC; i += 1024) m = fmaxf(m, d_rowmax[i]);
    m = blkMax(m, sh);
    float s = 0.f;
    for (int i = tid; i < TC; i += 1024) s += expf(d_rowmax[i] - m);
    s = blkSum(s, sh);
    float inv = 1.f/s;
    for (int i = tid; i < TC; i += 1024) d_alpha[i] = expf(d_rowmax[i] - m)*inv;
    if (tid < DD2) d_q2c[tid] = 0.f;
}

__global__ void k_q2c() {
    int j = blockIdx.x*256 + threadIdx.x;
    int t0 = blockIdx.y*128;
    if (j >= DD2) return;
    float s = 0.f;
    for (int t = t0; t < t0+128; ++t) s += d_alpha[t]*d_Cb[(size_t)t*DD2 + j];
    atomicAdd(&d_q2c[j], s);
}

__global__ void k_qac() {
    int i = blockIdx.x*256 + threadIdx.x;
    if (i >= TC*DD2) return;
    int t = i / DD2, j = i - t*DD2;
    float c = d_Cb[i], a = d_c2q[i];
    float* row = d_qac + (size_t)t*QACD;
    row[j]        = c;
    row[DD2 + j]  = a;
    row[2*DD2 + j]= c*a;
    row[3*DD2 + j]= c*d_q2c[j];
}

// logits[t] = qac[t].w[0:2848] + M[t].w[2848:3560]
__global__ void k_logits(const float* __restrict__ Mx, const float* __restrict__ w) {
    int t = blockIdx.x*8 + (threadIdx.x >> 5);
    int lane = threadIdx.x & 31;
    if (t >= TC) return;
    float s = 0.f;
    const float* qr = d_qac + (size_t)t*QACD;
    for (int k = lane; k < QACD; k += 32) s += qr[k]*w[k];
    const float* mr = Mx + (size_t)t*DD2;
    for (int k = lane; k < DD2; k += 32) s += mr[k]*w[QACD + k];
    #pragma unroll
    for (int off = 16; off; off >>= 1) s += __shfl_down_sync(0xffffffffu, s, off);
    if (lane == 0) d_lg[t] = s;
}

__global__ void k_smout(float* __restrict__ o) {
    __shared__ float sh[32];
    int tid = threadIdx.x;
    float m = -1e30f;
    for (int i = tid; i < TC; i += 1024) m = fmaxf(m, d_lg[i]);
    m = blkMax(m, sh);
    float s = 0.f;
    for (int i = tid; i < TC; i += 1024) s += expf(d_lg[i] - m);
    s = blkSum(s, sh);
    float inv = 1.f/s;
    for (int i = tid; i < TC; i += 1024) o[i] = expf(d_lg[i] - m)*inv;
}

// ---------------- host ----------------
static float* symaddr(const void* sym) {
    void* p = nullptr;
    cudaGetSymbolAddress(&p, sym);
    return (float*)p;
}

static void gemm(const float* A, const float* B, const float* bias, float* C,
                 int M, int N, int K)
{
    dim3 grid((N + 127)/128, (M + 127)/128);
    k_gemm_abt<<<grid, 256>>>(A, B, bias, C, M, N, K);
}

static void scan(const float* xWf, const float* xWb, const float* Whh,
                 const float* h0, float* out, int T)
{
    k_zeroflags<<<1, 128>>>();
    k_scan<<<2*NB, 1024>>>(xWf, xWb, Whh, h0, out, T);
}

extern "C" void kernel_launch(void* const* d_in, const int* in_sizes, int n_in,
                              void* d_out, int out_size)
{
    const int*   chars_ctx = (const int*)  d_in[0];
    const int*   chars_qry = (const int*)  d_in[1];
    const float* elmo_ctx  = (const float*)d_in[2];
    const float* elmo_qry  = (const float*)d_in[3];
    const float* char_emb  = (const float*)d_in[4];
    const float* conv_w    = (const float*)d_in[5];
    const float* conv_b    = (const float*)d_in[6];
    const float* hw_plain_w= (const float*)d_in[7];
    const float* hw_plain_b= (const float*)d_in[8];
    const float* hw_gate_w = (const float*)d_in[9];
    const float* hw_gate_b = (const float*)d_in[10];
    const float* ctx_Wih   = (const float*)d_in[11];
    const float* ctx_Whh   = (const float*)d_in[12];
    const float* ctx_b     = (const float*)d_in[13];
    const float* sim_w     = (const float*)d_in[14];
    const float* mod1_Wih  = (const float*)d_in[15];
    const float* mod1_Whh  = (const float*)d_in[16];
    const float* mod1_b    = (const float*)d_in[17];
    const float* mod2_Wih  = (const float*)d_in[18];
    const float* mod2_Whh  = (const float*)d_in[19];
    const float* mod2_b    = (const float*)d_in[20];
    const float* pos_Wih   = (const float*)d_in[21];
    const float* pos_Whh   = (const float*)d_in[22];
    const float* pos_b     = (const float*)d_in[23];
    const float* pos1_w    = (const float*)d_in[24];
    const float* pos2_w    = (const float*)d_in[25];
    const float* h0_ctx_c  = (const float*)d_in[26];
    const float* h0_ctx_q  = (const float*)d_in[27];
    const float* h0_mod    = (const float*)d_in[28];
    const float* h0_pos    = (const float*)d_in[29];
    float* out = (float*)d_out;

    float* x_ctx = symaddr(d_x_ctx);
    float* x_qry = symaddr(d_x_qry);
    float* t1    = symaddr(d_t1);
    float* t2    = symaddr(d_t2);
    float* xWf   = symaddr(d_xWf);
    float* xWb   = symaddr(d_xWb);
    float* Cb    = symaddr(d_Cb);
    float* Qb    = symaddr(d_Qb);
    float* Qt    = symaddr(d_Qt);
    float* CW    = symaddr(d_CW);
    float* sim   = symaddr(d_sim);
    float* cw    = symaddr(d_cw);
    float* qw    = symaddr(d_qw);
    float* c2q   = symaddr(d_c2q);
    float* qac   = symaddr(d_qac);
    float* Mb    = symaddr(d_Mb);
    float* M2b   = symaddr(d_M2b);

    // 1) char CNN + elmo concat
    k_convw<<<196, 256>>>(conv_w);
    k_charcnn<<<TC, 128>>>(chars_ctx, char_emb, conv_b, x_ctx);
    k_charcnn<<<TQ, 128>>>(chars_qry, char_emb, conv_b, x_qry);
    k_elmo<<<(TC*256 + 255)/256, 256>>>(elmo_ctx, x_ctx, TC);
    k_elmo<<<(TQ*256 + 255)/256, 256>>>(elmo_qry, x_qry, TQ);

    // 2) highway x2 (ctx and qry)
    for (int l = 0; l < 2; ++l) {
        gemm(x_ctx, hw_gate_w  + l*DHID*DHID, hw_gate_b  + l*DHID, t1, TC, DHID, DHID);
        gemm(x_ctx, hw_plain_w + l*DHID*DHID, hw_plain_b + l*DHID, t2, TC, DHID, DHID);
        k_hwy<<<(TC*DHID + 255)/256, 256>>>(x_ctx, t1, t2, TC*DHID);
        gemm(x_qry, hw_gate_w  + l*DHID*DHID, hw_gate_b  + l*DHID, t1, TQ, DHID, DHID);
        gemm(x_qry, hw_plain_w + l*DHID*DHID, hw_plain_b + l*DHID, t2, TQ, DHID, DHID);
        k_hwy<<<(TQ*DHID + 255)/256, 256>>>(x_qry, t1, t2, TQ*DHID);
    }

    // 3) context BiLSTM -> C
    gemm(x_ctx, ctx_Wih,             ctx_b,       xWf, TC, NGT, DHID);
    gemm(x_ctx, ctx_Wih + NGT*DHID,  ctx_b + NGT, xWb, TC, NGT, DHID);
    scan(xWf, xWb, ctx_Whh, h0_ctx_c, Cb, TC);

    // 4) query BiLSTM -> Q
    gemm(x_qry, ctx_Wih,             ctx_b,       xWf, TQ, NGT, DHID);
    gemm(x_qry, ctx_Wih + NGT*DHID,  ctx_b + NGT, xWb, TQ, NGT, DHID);
    scan(xWf, xWb, ctx_Whh, h0_ctx_q, Qb, TQ);

    // 5) attention
    k_rowdot<<<TC/8, 256>>>(Cb, sim_w,        cw, TC, DD2);
    k_rowdot<<<TQ/8, 256>>>(Qb, sim_w + DD2,  qw, TQ, DD2);
    k_scalecols<<<(TC*DD2 + 255)/256, 256>>>(Cb, sim_w + 2*DD2, CW, TC*DD2);
    gemm(CW, Qb, nullptr, sim, TC, TQ, DD2);      // (C*w_cq) @ Q^T
    k_simsm<<<TC/8, 256>>>();                     // + cw + qw, rowmax, softmax
    k_qt<<<(DD2*TQ + 255)/256, 256>>>();
    gemm(sim, Qt, nullptr, c2q, TC, DD2, TQ);     // attn @ Q
    k_alphasm<<<1, 1024>>>();
    { dim3 gq((DD2 + 255)/256, 32); k_q2c<<<gq, 256>>>(); }
    k_qac<<<(TC*DD2 + 255)/256, 256>>>();

    // 6) mod1 BiLSTM (input 2848) -> M
    gemm(qac, mod1_Wih,             mod1_b,       xWf, TC, NGT, QACD);
    gemm(qac, mod1_Wih + NGT*QACD,  mod1_b + NGT, xWb, TC, NGT, QACD);
    scan(xWf, xWb, mod1_Whh, h0_mod, Mb, TC);

    // 7) mod2 BiLSTM (input 712) -> M2
    gemm(Mb, mod2_Wih,            mod2_b,       xWf, TC, NGT, DD2);
    gemm(Mb, mod2_Wih + NGT*DD2,  mod2_b + NGT, xWb, TC, NGT, DD2);
    scan(xWf, xWb, mod2_Whh, h0_mod + 2*DHID, M2b, TC);

    // 8) pos1 = softmax([qac, M2] @ pos1_w)
    k_logits<<<TC/8, 256>>>(M2b, pos1_w);
    k_smout<<<1, 1024>>>(out);

    // 9) pos BiLSTM on M2 -> Mb (reuse), pos2
    gemm(M2b, pos_Wih,            pos_b,       xWf, TC, NGT, DD2);
    gemm(M2b, pos_Wih + NGT*DD2,  pos_b + NGT, xWb, TC, NGT, DD2);
    scan(xWf, xWb, pos_Whh, h0_pos, Mb, TC);
    k_logits<<<TC/8, 256>>>(Mb, pos2_w);
    k_smout<<<1, 1024>>>(out + TC);
}

// round 6
// speedup vs baseline: 1.7479x; 1.7479x over previous
#include <cuda_runtime.h>
#include <math.h>

#define TC   4096
#define TQ   128
#define DHID 356
#define DD2  712
#define NGT  1424
#define QACD 2848
#define UPB  8
#define NB   45      // ceil(356/8) blocks per direction

// ---------------- scratch (device globals; no allocation allowed) ----------------
__device__ float d_wt[5*100*100];
__device__ float d_x_ctx[TC*DHID];
__device__ float d_x_qry[TQ*DHID];
__device__ float d_t1[TC*DHID];
__device__ float d_t2[TC*DHID];
__device__ float d_xWf[TC*NGT];
__device__ float d_xWb[TC*NGT];
__device__ float d_Cb[TC*DD2];
__device__ float d_Qb[TQ*DD2];
__device__ float d_Qt[DD2*TQ];
__device__ float d_CW[TC*DD2];
__device__ float d_sim[TC*TQ];
__device__ float d_cw[TC];
__device__ float d_qw[TQ];
__device__ float d_rowmax[TC];
__device__ float d_alpha[TC];
__device__ float d_c2q[TC*DD2];
__device__ float d_q2c[DD2];
__device__ float d_qac[TC*QACD];
__device__ float d_Mb[TC*DD2];
__device__ float d_M2b[TC*DD2];
__device__ float d_lg[TC];
__device__ float g_hbuf[2][2][DHID];   // [dir][step parity][unit]
__device__ int   g_flags[2][64];       // [dir][block]

// ---------------- conv weight transpose: w[o][i][k] -> wt[k][i][o] ----------------
__global__ void k_convw(const float* __restrict__ w) {
    int idx = blockIdx.x*256 + threadIdx.x;
    if (idx < 50000) {
        int o = idx / 500; int r = idx - o*500; int i = r/5; int k = r - i*5;
        d_wt[(k*100+i)*100 + o] = w[idx];
    }
}

// ---------------- char CNN: one block per token ----------------
__global__ void k_charcnn(const int* __restrict__ chars, const float* __restrict__ emb,
                          const float* __restrict__ cb, float* __restrict__ xo)
{
    __shared__ float es[20][100];
    int t = blockIdx.x, tid = threadIdx.x;
    for (int idx = tid; idx < 2000; idx += 128) ((float*)es)[idx] = 0.f;
    __syncthreads();
    for (int idx = tid; idx < 1600; idx += 128) {
        int h = idx / 100, c = idx - h*100;
        es[h+2][c] = emb[chars[t*16+h]*100 + c];
    }
    __syncthreads();
    if (tid < 100) {
        float acc[16];
        float b = cb[tid];
        #pragma unroll
        for (int h = 0; h < 16; ++h) acc[h] = b;
        for (int i = 0; i < 100; ++i) {
            float ev[20];
            #pragma unroll
            for (int h2 = 0; h2 < 20; ++h2) ev[h2] = es[h2][i];
            #pragma unroll
            for (int k = 0; k < 5; ++k) {
                float wv = d_wt[(k*100+i)*100 + tid];
                #pragma unroll
                for (int h = 0; h < 16; ++h) acc[h] += ev[h+k]*wv;
            }
        }
        float m = acc[0];
        #pragma unroll
        for (int h = 1; h < 16; ++h) m = fmaxf(m, acc[h]);
        xo[t*DHID + tid] = m;
    }
}

// ---------------- elmo concat copy ----------------
__global__ void k_elmo(const float* __restrict__ e, float* __restrict__ xo, int T) {
    int idx = blockIdx.x*256 + threadIdx.x;
    if (idx < T*256) { int t = idx >> 8, j = idx & 255; xo[t*DHID + 100 + j] = e[idx]; }
}

// ---------------- SGEMM: C = A(MxK) * B(NxK)^T (+ bias[n]) ----------------
__global__ __launch_bounds__(256)
void k_gemm_abt(const float* __restrict__ A, const float* __restrict__ B,
                const float* __restrict__ bias, float* __restrict__ C,
                int M, int N, int K)
{
    __shared__ float As[8][132];
    __shared__ float Bs[8][132];
    int bm = blockIdx.y*128, bn = blockIdx.x*128;
    int tid = threadIdx.x;
    int tx = tid & 15, ty = tid >> 4;
    int lrow = tid >> 1;
    int lk4  = (tid & 1)*4;
    float acc[8][8];
    #pragma unroll
    for (int i = 0; i < 8; ++i)
        #pragma unroll
        for (int j = 0; j < 8; ++j) acc[i][j] = 0.f;
    int ar = bm + lrow;
    int br = bn + lrow;
    for (int kt = 0; kt < K; kt += 8) {
        float4 av = make_float4(0.f,0.f,0.f,0.f);
        float4 bv = make_float4(0.f,0.f,0.f,0.f);
        int ak = kt + lk4;
        if (ar < M && ak < K) av = *reinterpret_cast<const float4*>(A + (size_t)ar*K + ak);
        if (br < N && ak < K) bv = *reinterpret_cast<const float4*>(B + (size_t)br*K + ak);
        __syncthreads();
        As[lk4+0][lrow]=av.x; As[lk4+1][lrow]=av.y; As[lk4+2][lrow]=av.z; As[lk4+3][lrow]=av.w;
        Bs[lk4+0][lrow]=bv.x; Bs[lk4+1][lrow]=bv.y; Bs[lk4+2][lrow]=bv.z; Bs[lk4+3][lrow]=bv.w;
        __syncthreads();
        #pragma unroll
        for (int k = 0; k < 8; ++k) {
            float4 a0 = *reinterpret_cast<const float4*>(&As[k][ty*8]);
            float4 a1 = *reinterpret_cast<const float4*>(&As[k][ty*8+4]);
            float4 b0 = *reinterpret_cast<const float4*>(&Bs[k][tx*8]);
            float4 b1 = *reinterpret_cast<const float4*>(&Bs[k][tx*8+4]);
            float a[8] = {a0.x,a0.y,a0.z,a0.w,a1.x,a1.y,a1.z,a1.w};
            float b[8] = {b0.x,b0.y,b0.z,b0.w,b1.x,b1.y,b1.z,b1.w};
            #pragma unroll
            for (int i = 0; i < 8; ++i)
                #pragma unroll
                for (int j = 0; j < 8; ++j) acc[i][j] += a[i]*b[j];
        }
    }
    #pragma unroll
    for (int i = 0; i < 8; ++i) {
        int row = bm + ty*8 + i;
        if (row >= M) continue;
        #pragma unroll
        for (int j = 0; j < 8; ++j) {
            int col = bn + tx*8 + j;
            if (col < N) {
                float v = acc[i][j];
                if (bias) v += bias[col];
                C[(size_t)row*N + col] = v;
            }
        }
    }
}

// ---------------- highway combine ----------------
__global__ void k_hwy(float* __restrict__ x, const float* __restrict__ g,
                      const float* __restrict__ p, int n)
{
    int i = blockIdx.x*256 + threadIdx.x;
    if (i < n) {
        float gv = 1.f/(1.f + expf(-g[i]));
        float pv = fmaxf(p[i], 0.f);
        x[i] = gv*pv + (1.f - gv)*x[i];
    }
}

// ---------------- flag reset before each scan ----------------
__global__ void k_zeroflags() {
    int i = threadIdx.x;
    if (i < 128) ((int*)g_flags)[i] = 0;
}

// ---------------- persistent BiLSTM scan (both directions in one launch) ----------
// 45 blocks/direction, 8 units/block, 1024 threads (32 warps = 32 gate rows).
// Flag-array barrier where ONLY warp 1 polls (90 polling warps chip-wide, not
// 2880 — R4's all-warp polling storm serialized the flag LTS slice and cost
// ~13us/step). Other warps park at __syncthreads. Double-buffered h by parity.
__global__ __launch_bounds__(1024, 1)
void k_scan(const float* __restrict__ xWf, const float* __restrict__ xWb,
            const float* __restrict__ Whh, const float* __restrict__ h0,
            float* __restrict__ out, int T)
{
    __shared__ float ws[32][DHID];
    __shared__ float zred[32];
    __shared__ float cs[UPB];
    int dir = blockIdx.x / NB;
    int blk = blockIdx.x - dir*NB;
    int tid = threadIdx.x;
    int warp = tid >> 5, lane = tid & 31;
    const float* xW = dir ? xWb : xWf;
    const float* W  = Whh + (size_t)dir*NGT*DHID;
    int u0 = blk*UPB;

    int r  = warp;                 // gate row: r = g*8 + ui
    int gg = r >> 3, ui = r & 7;
    int uu_r = u0 + ui;
    int j  = gg*DHID + uu_r;       // row in [0,1424)
    bool rowvalid = (uu_r < DHID);

    // load this block's 32 Whh rows into smem
    for (int idx = tid; idx < 32*DHID; idx += 1024) {
        int rr = idx / DHID, k = idx - rr*DHID;
        int g2 = rr >> 3, u2 = rr & 7;
        ws[rr][k] = (u0+u2 < DHID) ? W[(size_t)(g2*DHID + u0 + u2)*DHID + k] : 0.f;
    }
    // h(t-1) registers (from h0)
    float hreg[12];
    #pragma unroll
    for (int i = 0; i < 11; ++i) hreg[i] = h0[dir*DHID + lane + 32*i];
    hreg[11] = (lane < 4) ? h0[dir*DHID + 352 + lane] : 0.f;
    if (tid < UPB) cs[tid] = (u0+tid < DHID) ? h0[dir*DHID + u0 + tid] : 0.f;

    float xw = 0.f;
    if (lane == 0 && rowvalid) {
        int ti0 = dir ? (T-1) : 0;
        xw = __ldg(&xW[(size_t)ti0*NGT + j]);
    }
    __syncthreads();

    volatile int* flags = &g_flags[dir][0];

    for (int t = 0; t < T; ++t) {
        int ti = dir ? (T-1-t) : t;
        // --- h @ Whh^T for this warp's gate row ---
        float s = 0.f;
        #pragma unroll
        for (int i = 0; i < 11; ++i) s += ws[r][lane + 32*i]*hreg[i];
        if (lane < 4) s += ws[r][352 + lane]*hreg[11];
        #pragma unroll
        for (int o = 16; o; o >>= 1) s += __shfl_down_sync(0xffffffffu, s, o);
        if (lane == 0) zred[r] = s + xw;
        __syncthreads();

        if (warp == 0) {
            // 32 lanes: one activation each, gather via shfl
            float z = zred[lane];
            float a = ((lane >> 3) == 2) ? tanhf(z)
                                         : __fdividef(1.f, 1.f + __expf(-z));
            int u = lane & 7;
            float si = __shfl_sync(0xffffffffu, a, u);
            float sf = __shfl_sync(0xffffffffu, a, 8 + u);
            float tg = __shfl_sync(0xffffffffu, a, 16 + u);
            float so = __shfl_sync(0xffffffffu, a, 24 + u);
            int uu = u0 + lane;
            if (lane < UPB && uu < DHID) {
                float c = sf*cs[lane] + si*tg;
                float h = so*tanhf(c);
                cs[lane] = c;
                volatile float* hw = &g_hbuf[dir][t & 1][0];
                hw[uu] = h;
                out[(size_t)ti*DD2 + dir*DHID + uu] = h;
            }
            __threadfence();                 // h visible at GPU scope...
            __syncwarp(0xffffffffu);
            if (lane == 0) flags[blk] = t + 1;   // ...before release flag
        }
        // prefetch next step's xW (issued, then warp parks at the barrier)
        if (lane == 0 && rowvalid && t + 1 < T) {
            int tn = dir ? (T-2-t) : (t+1);
            xw = __ldg(&xW[(size_t)tn*NGT + j]);
        }
        // ONLY warp 1 polls the 45 flags
        if (warp == 1 && t + 1 < T) {
            int tgt = t + 1;
            for (;;) {
                int v0 = (lane       < NB) ? flags[lane]      : tgt;
                int v1 = (lane + 32  < NB) ? flags[lane + 32] : tgt;
                if (__all_sync(0xffffffffu, (v0 >= tgt) && (v1 >= tgt))) break;
            }
        }
        __syncthreads();                     // release all warps after poll
        if (t + 1 < T) {
            volatile float* hr = &g_hbuf[dir][t & 1][0];
            #pragma unroll
            for (int i = 0; i < 11; ++i) hreg[i] = hr[lane + 32*i];
            if (lane < 4) hreg[11] = hr[352 + lane];
        }
    }
}

// ---------------- row dot (gemv): o[t] = X[t,:K] . w ----------------
__global__ void k_rowdot(const float* __restrict__ X, const float* __restrict__ w,
                         float* __restrict__ o, int T, int K)
{
    int t = blockIdx.x*8 + (threadIdx.x >> 5);
    int lane = threadIdx.x & 31;
    if (t >= T) return;
    float s = 0.f;
    for (int k = lane; k < K; k += 32) s += X[(size_t)t*K + k]*w[k];
    #pragma unroll
    for (int off = 16; off; off >>= 1) s += __shfl_down_sync(0xffffffffu, s, off);
    if (lane == 0) o[t] = s;
}

__global__ void k_scalecols(const float* __restrict__ C, const float* __restrict__ w,
                            float* __restrict__ o, int n)
{
    int i = blockIdx.x*256 + threadIdx.x;
    if (i < n) o[i] = C[i]*w[i % DD2];
}

__global__ void k_qt() {
    int i = blockIdx.x*256 + threadIdx.x;
    if (i < DD2*TQ) { int j = i / TQ, q = i - j*TQ; d_Qt[i] = d_Qb[q*DD2 + j]; }
}

// sim[t][q] += cw[t]+qw[q]; rowmax; row softmax in-place
__global__ void k_simsm() {
    int t = blockIdx.x*8 + (threadIdx.x >> 5);
    int lane = threadIdx.x & 31;
    if (t >= TC) return;
    float cw = d_cw[t];
    float v[4];
    float m = -1e30f;
    #pragma unroll
    for (int i = 0; i < 4; ++i) {
        int q = lane + 32*i;
        v[i] = d_sim[t*TQ + q] + cw + d_qw[q];
        m = fmaxf(m, v[i]);
    }
    #pragma unroll
    for (int off = 16; off; off >>= 1) m = fmaxf(m, __shfl_xor_sync(0xffffffffu, m, off));
    float s = 0.f;
    #pragma unroll
    for (int i = 0; i < 4; ++i) { v[i] = expf(v[i]-m); s += v[i]; }
    #pragma unroll
    for (int off = 16; off; off >>= 1) s += __shfl_xor_sync(0xffffffffu, s, off);
    float inv = 1.f/s;
    #pragma unroll
    for (int i = 0; i < 4; ++i) d_sim[t*TQ + lane + 32*i] = v[i]*inv;
    if (lane == 0) d_rowmax[t] = m;
}

__device__ __forceinline__ float blkMax(float v, float* sh) {
    int lane = threadIdx.x & 31, w = threadIdx.x >> 5;
    #pragma unroll
    for (int o = 16; o; o >>= 1) v = fmaxf(v, __shfl_xor_sync(0xffffffffu, v, o));
    if (lane == 0) sh[w] = v;
    __syncthreads();
    if (w == 0) {
        float x = sh[lane];
        #pragma unroll
        for (int o = 16; o; o >>= 1) x = fmaxf(x, __shfl_xor_sync(0xffffffffu, x, o));
        if (lane == 0) sh[0] = x;
    }
    __syncthreads();
    float r = sh[0];
    __syncthreads();
    return r;
}
__device__ __forceinline__ float blkSum(float v, float* sh) {
    int lane = threadIdx.x & 31, w = threadIdx.x >> 5;
    #pragma unroll
    for (int o = 16; o; o >>= 1) v += __shfl_xor_sync(0xffffffffu, v, o);
    if (lane == 0) sh[w] = v;
    __syncthreads();
    if (w == 0) {
        float x = sh[lane];
        #pragma unroll
        for (int o = 16; o; o >>= 1) x += __shfl_xor_sync(0xffffffffu, x, o);
        if (lane == 0) sh[0] = x;
    }
    __syncthreads();
    float r = sh[0];
    __syncthreads();
    return r;
}

// softmax over rowmax (4096) -> alpha; also zero q2c
__global__ void k_alphasm() {
    __shared__ float sh[32];
    int tid = threadIdx.x;
    float m = -1e30f;
    for (int i = tid; i < TC; i += 1024) m = fmaxf(m, d_rowmax[i]);
    m = blkMax(m, sh);
    float s = 0.f;
    for (int i = tid; i < TC; i += 1024) s += expf(d_rowmax[i] - m);
    s = blkSum(s, sh);
    float inv = 1.f/s;
    for (int i = tid; i < TC; i += 1024) d_alpha[i] = expf(d_rowmax[i] - m)*inv;
    if (tid < DD2) d_q2c[tid] = 0.f;
}

__global__ void k_q2c() {
    int j = blockIdx.x*256 + threadIdx.x;
    int t0 = blockIdx.y*128;
    if (j >= DD2) return;
    float s = 0.f;
    for (int t = t0; t < t0+128; ++t) s += d_alpha[t]*d_Cb[(size_t)t*DD2 + j];
    atomicAdd(&d_q2c[j], s);
}

__global__ void k_qac() {
    int i = blockIdx.x*256 + threadIdx.x;
    if (i >= TC*DD2) return;
    int t = i / DD2, j = i - t*DD2;
    float c = d_Cb[i], a = d_c2q[i];
    float* row = d_qac + (size_t)t*QACD;
    row[j]        = c;
    row[DD2 + j]  = a;
    row[2*DD2 + j]= c*a;
    row[3*DD2 + j]= c*d_q2c[j];
}

// logits[t] = qac[t].w[0:2848] + M[t].w[2848:3560]
__global__ void k_logits(const float* __restrict__ Mx, const float* __restrict__ w) {
    int t = blockIdx.x*8 + (threadIdx.x >> 5);
    int lane = threadIdx.x & 31;
    if (t >= TC) return;
    float s = 0.f;
    const float* qr = d_qac + (size_t)t*QACD;
    for (int k = lane; k < QACD; k += 32) s += qr[k]*w[k];
    const float* mr = Mx + (size_t)t*DD2;
    for (int k = lane; k < DD2; k += 32) s += mr[k]*w[QACD + k];
    #pragma unroll
    for (int off = 16; off; off >>= 1) s += __shfl_down_sync(0xffffffffu, s, off);
    if (lane == 0) d_lg[t] = s;
}

__global__ void k_smout(float* __restrict__ o) {
    __shared__ float sh[32];
    int tid = threadIdx.x;
    float m = -1e30f;
    for (int i = tid; i < TC; i += 1024) m = fmaxf(m, d_lg[i]);
    m = blkMax(m, sh);
    float s = 0.f;
    for (int i = tid; i < TC; i += 1024) s += expf(d_lg[i] - m);
    s = blkSum(s, sh);
    float inv = 1.f/s;
    for (int i = tid; i < TC; i += 1024) o[i] = expf(d_lg[i] - m)*inv;
}

// ---------------- host ----------------
static float* symaddr(const void* sym) {
    void* p = nullptr;
    cudaGetSymbolAddress(&p, sym);
    return (float*)p;
}

static void gemm(const float* A, const float* B, const float* bias, float* C,
                 int M, int N, int K)
{
    dim3 grid((N + 127)/128, (M + 127)/128);
    k_gemm_abt<<<grid, 256>>>(A, B, bias, C, M, N, K);
}

static void scan(const float* xWf, const float* xWb, const float* Whh,
                 const float* h0, float* out, int T)
{
    k_zeroflags<<<1, 128>>>();
    k_scan<<<2*NB, 1024>>>(xWf, xWb, Whh, h0, out, T);
}

extern "C" void kernel_launch(void* const* d_in, const int* in_sizes, int n_in,
                              void* d_out, int out_size)
{
    const int*   chars_ctx = (const int*)  d_in[0];
    const int*   chars_qry = (const int*)  d_in[1];
    const float* elmo_ctx  = (const float*)d_in[2];
    const float* elmo_qry  = (const float*)d_in[3];
    const float* char_emb  = (const float*)d_in[4];
    const float* conv_w    = (const float*)d_in[5];
    const float* conv_b    = (const float*)d_in[6];
    const float* hw_plain_w= (const float*)d_in[7];
    const float* hw_plain_b= (const float*)d_in[8];
    const float* hw_gate_w = (const float*)d_in[9];
    const float* hw_gate_b = (const float*)d_in[10];
    const float* ctx_Wih   = (const float*)d_in[11];
    const float* ctx_Whh   = (const float*)d_in[12];
    const float* ctx_b     = (const float*)d_in[13];
    const float* sim_w     = (const float*)d_in[14];
    const float* mod1_Wih  = (const float*)d_in[15];
    const float* mod1_Whh  = (const float*)d_in[16];
    const float* mod1_b    = (const float*)d_in[17];
    const float* mod2_Wih  = (const float*)d_in[18];
    const float* mod2_Whh  = (const float*)d_in[19];
    const float* mod2_b    = (const float*)d_in[20];
    const float* pos_Wih   = (const float*)d_in[21];
    const float* pos_Whh   = (const float*)d_in[22];
    const float* pos_b     = (const float*)d_in[23];
    const float* pos1_w    = (const float*)d_in[24];
    const float* pos2_w    = (const float*)d_in[25];
    const float* h0_ctx_c  = (const float*)d_in[26];
    const float* h0_ctx_q  = (const float*)d_in[27];
    const float* h0_mod    = (const float*)d_in[28];
    const float* h0_pos    = (const float*)d_in[29];
    float* out = (float*)d_out;

    float* x_ctx = symaddr(d_x_ctx);
    float* x_qry = symaddr(d_x_qry);
    float* t1    = symaddr(d_t1);
    float* t2    = symaddr(d_t2);
    float* xWf   = symaddr(d_xWf);
    float* xWb   = symaddr(d_xWb);
    float* Cb    = symaddr(d_Cb);
    float* Qb    = symaddr(d_Qb);
    float* Qt    = symaddr(d_Qt);
    float* CW    = symaddr(d_CW);
    float* sim   = symaddr(d_sim);
    float* cw    = symaddr(d_cw);
    float* qw    = symaddr(d_qw);
    float* c2q   = symaddr(d_c2q);
    float* qac   = symaddr(d_qac);
    float* Mb    = symaddr(d_Mb);
    float* M2b   = symaddr(d_M2b);

    // 1) char CNN + elmo concat
    k_convw<<<196, 256>>>(conv_w);
    k_charcnn<<<TC, 128>>>(chars_ctx, char_emb, conv_b, x_ctx);
    k_charcnn<<<TQ, 128>>>(chars_qry, char_emb, conv_b, x_qry);
    k_elmo<<<(TC*256 + 255)/256, 256>>>(elmo_ctx, x_ctx, TC);
    k_elmo<<<(TQ*256 + 255)/256, 256>>>(elmo_qry, x_qry, TQ);

    // 2) highway x2 (ctx and qry)
    for (int l = 0; l < 2; ++l) {
        gemm(x_ctx, hw_gate_w  + l*DHID*DHID, hw_gate_b  + l*DHID, t1, TC, DHID, DHID);
        gemm(x_ctx, hw_plain_w + l*DHID*DHID, hw_plain_b + l*DHID, t2, TC, DHID, DHID);
        k_hwy<<<(TC*DHID + 255)/256, 256>>>(x_ctx, t1, t2, TC*DHID);
        gemm(x_qry, hw_gate_w  + l*DHID*DHID, hw_gate_b  + l*DHID, t1, TQ, DHID, DHID);
        gemm(x_qry, hw_plain_w + l*DHID*DHID, hw_plain_b + l*DHID, t2, TQ, DHID, DHID);
        k_hwy<<<(TQ*DHID + 255)/256, 256>>>(x_qry, t1, t2, TQ*DHID);
    }

    // 3) context BiLSTM -> C
    gemm(x_ctx, ctx_Wih,             ctx_b,       xWf, TC, NGT, DHID);
    gemm(x_ctx, ctx_Wih + NGT*DHID,  ctx_b + NGT, xWb, TC, NGT, DHID);
    scan(xWf, xWb, ctx_Whh, h0_ctx_c, Cb, TC);

    // 4) query BiLSTM -> Q
    gemm(x_qry, ctx_Wih,             ctx_b,       xWf, TQ, NGT, DHID);
    gemm(x_qry, ctx_Wih + NGT*DHID,  ctx_b + NGT, xWb, TQ, NGT, DHID);
    scan(xWf, xWb, ctx_Whh, h0_ctx_q, Qb, TQ);

    // 5) attention
    k_rowdot<<<TC/8, 256>>>(Cb, sim_w,        cw, TC, DD2);
    k_rowdot<<<TQ/8, 256>>>(Qb, sim_w + DD2,  qw, TQ, DD2);
    k_scalecols<<<(TC*DD2 + 255)/256, 256>>>(Cb, sim_w + 2*DD2, CW, TC*DD2);
    gemm(CW, Qb, nullptr, sim, TC, TQ, DD2);      // (C*w_cq) @ Q^T
    k_simsm<<<TC/8, 256>>>();                     // + cw + qw, rowmax, softmax
    k_qt<<<(DD2*TQ + 255)/256, 256>>>();
    gemm(sim, Qt, nullptr, c2q, TC, DD2, TQ);     // attn @ Q
    k_alphasm<<<1, 1024>>>();
    { dim3 gq((DD2 + 255)/256, 32); k_q2c<<<gq, 256>>>(); }
    k_qac<<<(TC*DD2 + 255)/256, 256>>>();

    // 6) mod1 BiLSTM (input 2848) -> M
    gemm(qac, mod1_Wih,             mod1_b,       xWf, TC, NGT, QACD);
    gemm(qac, mod1_Wih + NGT*QACD,  mod1_b + NGT, xWb, TC, NGT, QACD);
    scan(xWf, xWb, mod1_Whh, h0_mod, Mb, TC);

    // 7) mod2 BiLSTM (input 712) -> M2
    gemm(Mb, mod2_Wih,            mod2_b,       xWf, TC, NGT, DD2);
    gemm(Mb, mod2_Wih + NGT*DD2,  mod2_b + NGT, xWb, TC, NGT, DD2);
    scan(xWf, xWb, mod2_Whh, h0_mod + 2*DHID, M2b, TC);

    // 8) pos1 = softmax([qac, M2] @ pos1_w)
    k_logits<<<TC/8, 256>>>(M2b, pos1_w);
    k_smout<<<1, 1024>>>(out);

    // 9) pos BiLSTM on M2 -> Mb (reuse), pos2
    gemm(M2b, pos_Wih,            pos_b,       xWf, TC, NGT, DD2);
    gemm(M2b, pos_Wih + NGT*DD2,  pos_b + NGT, xWb, TC, NGT, DD2);
    scan(xWf, xWb, pos_Whh, h0_pos, Mb, TC);
    k_logits<<<TC/8, 256>>>(Mb, pos2_w);
    k_smout<<<1, 1024>>>(out + TC);
}

// round 7
// speedup vs baseline: 4.4303x; 2.5347x over previous
#include <cuda_runtime.h>
#include <math.h>

#define TC   4096
#define TQ   128
#define DHID 356
#define DD2  712
#define NGT  1424
#define QACD 2848
#define UPB  8
#define NB   45      // ceil(356/8) blocks per direction

// ---------------- scratch (device globals; no allocation allowed) ----------------
__device__ float d_wt[5*100*100];
__device__ float d_x_ctx[TC*DHID];
__device__ float d_x_qry[TQ*DHID];
__device__ float d_t1[TC*DHID];
__device__ float d_t2[TC*DHID];
__device__ float d_xWf[TC*NGT];
__device__ float d_xWb[TC*NGT];
__device__ float d_Cb[TC*DD2];
__device__ float d_Qb[TQ*DD2];
__device__ float d_Qt[DD2*TQ];
__device__ float d_CW[TC*DD2];
__device__ float d_sim[TC*TQ];
__device__ float d_cw[TC];
__device__ float d_qw[TQ];
__device__ float d_rowmax[TC];
__device__ float d_alpha[TC];
__device__ float d_c2q[TC*DD2];
__device__ float d_q2c[DD2];
__device__ float d_qac[TC*QACD];
__device__ float d_Mb[TC*DD2];
__device__ float d_M2b[TC*DD2];
__device__ float d_lg[TC];
__device__ float g_hbuf[2][2][DHID];   // [dir][step parity][unit]
__device__ int   g_flags[2][64];       // [dir][block]

// ---------------- conv weight transpose: w[o][i][k] -> wt[k][i][o] ----------------
__global__ void k_convw(const float* __restrict__ w) {
    int idx = blockIdx.x*256 + threadIdx.x;
    if (idx < 50000) {
        int o = idx / 500; int r = idx - o*500; int i = r/5; int k = r - i*5;
        d_wt[(k*100+i)*100 + o] = w[idx];
    }
}

// ---------------- char CNN: one block per token ----------------
__global__ void k_charcnn(const int* __restrict__ chars, const float* __restrict__ emb,
                          const float* __restrict__ cb, float* __restrict__ xo)
{
    __shared__ float es[20][100];
    int t = blockIdx.x, tid = threadIdx.x;
    for (int idx = tid; idx < 2000; idx += 128) ((float*)es)[idx] = 0.f;
    __syncthreads();
    for (int idx = tid; idx < 1600; idx += 128) {
        int h = idx / 100, c = idx - h*100;
        es[h+2][c] = emb[chars[t*16+h]*100 + c];
    }
    __syncthreads();
    if (tid < 100) {
        float acc[16];
        float b = cb[tid];
        #pragma unroll
        for (int h = 0; h < 16; ++h) acc[h] = b;
        for (int i = 0; i < 100; ++i) {
            float ev[20];
            #pragma unroll
            for (int h2 = 0; h2 < 20; ++h2) ev[h2] = es[h2][i];
            #pragma unroll
            for (int k = 0; k < 5; ++k) {
                float wv = d_wt[(k*100+i)*100 + tid];
                #pragma unroll
                for (int h = 0; h < 16; ++h) acc[h] += ev[h+k]*wv;
            }
        }
        float m = acc[0];
        #pragma unroll
        for (int h = 1; h < 16; ++h) m = fmaxf(m, acc[h]);
        xo[t*DHID + tid] = m;
    }
}

// ---------------- elmo concat copy ----------------
__global__ void k_elmo(const float* __restrict__ e, float* __restrict__ xo, int T) {
    int idx = blockIdx.x*256 + threadIdx.x;
    if (idx < T*256) { int t = idx >> 8, j = idx & 255; xo[t*DHID + 100 + j] = e[idx]; }
}

// ---------------- SGEMM: C = A(MxK) * B(NxK)^T (+ bias[n]) ----------------
__global__ __launch_bounds__(256)
void k_gemm_abt(const float* __restrict__ A, const float* __restrict__ B,
                const float* __restrict__ bias, float* __restrict__ C,
                int M, int N, int K)
{
    __shared__ float As[8][132];
    __shared__ float Bs[8][132];
    int bm = blockIdx.y*128, bn = blockIdx.x*128;
    int tid = threadIdx.x;
    int tx = tid & 15, ty = tid >> 4;
    int lrow = tid >> 1;
    int lk4  = (tid & 1)*4;
    float acc[8][8];
    #pragma unroll
    for (int i = 0; i < 8; ++i)
        #pragma unroll
        for (int j = 0; j < 8; ++j) acc[i][j] = 0.f;
    int ar = bm + lrow;
    int br = bn + lrow;
    for (int kt = 0; kt < K; kt += 8) {
        float4 av = make_float4(0.f,0.f,0.f,0.f);
        float4 bv = make_float4(0.f,0.f,0.f,0.f);
        int ak = kt + lk4;
        if (ar < M && ak < K) av = *reinterpret_cast<const float4*>(A + (size_t)ar*K + ak);
        if (br < N && ak < K) bv = *reinterpret_cast<const float4*>(B + (size_t)br*K + ak);
        __syncthreads();
        As[lk4+0][lrow]=av.x; As[lk4+1][lrow]=av.y; As[lk4+2][lrow]=av.z; As[lk4+3][lrow]=av.w;
        Bs[lk4+0][lrow]=bv.x; Bs[lk4+1][lrow]=bv.y; Bs[lk4+2][lrow]=bv.z; Bs[lk4+3][lrow]=bv.w;
        __syncthreads();
        #pragma unroll
        for (int k = 0; k < 8; ++k) {
            float4 a0 = *reinterpret_cast<const float4*>(&As[k][ty*8]);
            float4 a1 = *reinterpret_cast<const float4*>(&As[k][ty*8+4]);
            float4 b0 = *reinterpret_cast<const float4*>(&Bs[k][tx*8]);
            float4 b1 = *reinterpret_cast<const float4*>(&Bs[k][tx*8+4]);
            float a[8] = {a0.x,a0.y,a0.z,a0.w,a1.x,a1.y,a1.z,a1.w};
            float b[8] = {b0.x,b0.y,b0.z,b0.w,b1.x,b1.y,b1.z,b1.w};
            #pragma unroll
            for (int i = 0; i < 8; ++i)
                #pragma unroll
                for (int j = 0; j < 8; ++j) acc[i][j] += a[i]*b[j];
        }
    }
    #pragma unroll
    for (int i = 0; i < 8; ++i) {
        int row = bm + ty*8 + i;
        if (row >= M) continue;
        #pragma unroll
        for (int j = 0; j < 8; ++j) {
            int col = bn + tx*8 + j;
            if (col < N) {
                float v = acc[i][j];
                if (bias) v += bias[col];
                C[(size_t)row*N + col] = v;
            }
        }
    }
}

// ---------------- highway combine ----------------
__global__ void k_hwy(float* __restrict__ x, const float* __restrict__ g,
                      const float* __restrict__ p, int n)
{
    int i = blockIdx.x*256 + threadIdx.x;
    if (i < n) {
        float gv = 1.f/(1.f + expf(-g[i]));
        float pv = fmaxf(p[i], 0.f);
        x[i] = gv*pv + (1.f - gv)*x[i];
    }
}

// ---------------- flag reset before each scan ----------------
__global__ void k_zeroflags() {
    int i = threadIdx.x;
    if (i < 128) ((int*)g_flags)[i] = 0;
}

// ---------------- persistent BiLSTM scan (both directions in one launch) ----------
// 45 blocks/direction, 8 units/block, 1024 threads (32 warps = 32 gate rows).
// Per-step protocol: smem gemv -> warp0 activations + h publish + flag release;
// warp1 (only) polls the 45 flags; then the WHOLE BLOCK loads h ONCE into smem
// (1 element/thread). R5's bug: every warp reloaded all 356 h's via volatile
// LDG -> 2880 L2 accesses per line per step -> ~6.6us/step of LTS serialization.
__global__ __launch_bounds__(1024, 1)
void k_scan(const float* __restrict__ xWf, const float* __restrict__ xWb,
            const float* __restrict__ Whh, const float* __restrict__ h0,
            float* __restrict__ out, int T)
{
    __shared__ float ws[32][DHID];
    __shared__ float hs[DHID];
    __shared__ float zred[32];
    __shared__ float cs[UPB];
    int dir = blockIdx.x / NB;
    int blk = blockIdx.x - dir*NB;
    int tid = threadIdx.x;
    int warp = tid >> 5, lane = tid & 31;
    const float* xW = dir ? xWb : xWf;
    const float* W  = Whh + (size_t)dir*NGT*DHID;
    int u0 = blk*UPB;

    int r  = warp;                 // gate row: r = g*8 + ui
    int gg = r >> 3, ui = r & 7;
    int uu_r = u0 + ui;
    int j  = gg*DHID + uu_r;       // row in [0,1424)
    bool rowvalid = (uu_r < DHID);

    // load this block's 32 Whh rows into smem
    for (int idx = tid; idx < 32*DHID; idx += 1024) {
        int rr = idx / DHID, k = idx - rr*DHID;
        int g2 = rr >> 3, u2 = rr & 7;
        ws[rr][k] = (u0+u2 < DHID) ? W[(size_t)(g2*DHID + u0 + u2)*DHID + k] : 0.f;
    }
    if (tid < DHID) hs[tid] = h0[dir*DHID + tid];
    if (tid < UPB)  cs[tid] = (u0+tid < DHID) ? h0[dir*DHID + u0 + tid] : 0.f;

    float xw = 0.f;
    if (lane == 0 && rowvalid) {
        int ti0 = dir ? (T-1) : 0;
        xw = __ldg(&xW[(size_t)ti0*NGT + j]);
    }
    __syncthreads();

    volatile int* flags = &g_flags[dir][0];

    for (int t = 0; t < T; ++t) {
        int ti = dir ? (T-1-t) : t;
        // --- h @ Whh^T for this warp's gate row (all operands in smem) ---
        float s = 0.f;
        #pragma unroll
        for (int i = 0; i < 11; ++i) s += ws[r][lane + 32*i]*hs[lane + 32*i];
        if (lane < 4) s += ws[r][352 + lane]*hs[352 + lane];
        #pragma unroll
        for (int o = 16; o; o >>= 1) s += __shfl_down_sync(0xffffffffu, s, o);
        if (lane == 0) zred[r] = s + xw;
        __syncthreads();

        if (warp == 0) {
            // 32 lanes: one activation each, gather via shfl
            float z = zred[lane];
            float a = ((lane >> 3) == 2) ? tanhf(z)
                                         : __fdividef(1.f, 1.f + __expf(-z));
            int u = lane & 7;
            float si = __shfl_sync(0xffffffffu, a, u);
            float sf = __shfl_sync(0xffffffffu, a, 8 + u);
            float tg = __shfl_sync(0xffffffffu, a, 16 + u);
            float so = __shfl_sync(0xffffffffu, a, 24 + u);
            int uu = u0 + lane;
            float h = 0.f;
            bool act = (lane < UPB) && (uu < DHID);
            if (act) {
                float c = sf*cs[lane] + si*tg;
                h = so*tanhf(c);
                cs[lane] = c;
                volatile float* hw = &g_hbuf[dir][t & 1][0];
                hw[uu] = h;
            }
            __threadfence();                 // h visible at GPU scope...
            __syncwarp(0xffffffffu);
            if (lane == 0) flags[blk] = t + 1;   // ...before release flag
            if (act) out[(size_t)ti*DD2 + dir*DHID + uu] = h;  // off critical path
        }
        // prefetch next step's xW (issued, then warp parks at the barrier)
        if (lane == 0 && rowvalid && t + 1 < T) {
            int tn = dir ? (T-2-t) : (t+1);
            xw = __ldg(&xW[(size_t)tn*NGT + j]);
        }
        // ONLY warp 1 polls the 45 flags
        if (warp == 1 && t + 1 < T) {
            int tgt = t + 1;
            for (;;) {
                int v0 = (lane       < NB) ? flags[lane]      : tgt;
                int v1 = (lane + 32  < NB) ? flags[lane + 32] : tgt;
                if (__all_sync(0xffffffffu, (v0 >= tgt) && (v1 >= tgt))) break;
            }
        }
        __syncthreads();                     // release all warps after poll
        if (t + 1 < T) {
            // ONE coalesced h reload per block: 1 element/thread
            if (tid < DHID) {
                volatile float* hr = &g_hbuf[dir][t & 1][0];
                hs[tid] = hr[tid];
            }
            __syncthreads();
        }
    }
}

// ---------------- row dot (gemv): o[t] = X[t,:K] . w ----------------
__global__ void k_rowdot(const float* __restrict__ X, const float* __restrict__ w,
                         float* __restrict__ o, int T, int K)
{
    int t = blockIdx.x*8 + (threadIdx.x >> 5);
    int lane = threadIdx.x & 31;
    if (t >= T) return;
    float s = 0.f;
    for (int k = lane; k < K; k += 32) s += X[(size_t)t*K + k]*w[k];
    #pragma unroll
    for (int off = 16; off; off >>= 1) s += __shfl_down_sync(0xffffffffu, s, off);
    if (lane == 0) o[t] = s;
}

__global__ void k_scalecols(const float* __restrict__ C, const float* __restrict__ w,
                            float* __restrict__ o, int n)
{
    int i = blockIdx.x*256 + threadIdx.x;
    if (i < n) o[i] = C[i]*w[i % DD2];
}

__global__ void k_qt() {
    int i = blockIdx.x*256 + threadIdx.x;
    if (i < DD2*TQ) { int j = i / TQ, q = i - j*TQ; d_Qt[i] = d_Qb[q*DD2 + j]; }
}

// sim[t][q] += cw[t]+qw[q]; rowmax; row softmax in-place
__global__ void k_simsm() {
    int t = blockIdx.x*8 + (threadIdx.x >> 5);
    int lane = threadIdx.x & 31;
    if (t >= TC) return;
    float cw = d_cw[t];
    float v[4];
    float m = -1e30f;
    #pragma unroll
    for (int i = 0; i < 4; ++i) {
        int q = lane + 32*i;
        v[i] = d_sim[t*TQ + q] + cw + d_qw[q];
        m = fmaxf(m, v[i]);
    }
    #pragma unroll
    for (int off = 16; off; off >>= 1) m = fmaxf(m, __shfl_xor_sync(0xffffffffu, m, off));
    float s = 0.f;
    #pragma unroll
    for (int i = 0; i < 4; ++i) { v[i] = expf(v[i]-m); s += v[i]; }
    #pragma unroll
    for (int off = 16; off; off >>= 1) s += __shfl_xor_sync(0xffffffffu, s, off);
    float inv = 1.f/s;
    #pragma unroll
    for (int i = 0; i < 4; ++i) d_sim[t*TQ + lane + 32*i] = v[i]*inv;
    if (lane == 0) d_rowmax[t] = m;
}

__device__ __forceinline__ float blkMax(float v, float* sh) {
    int lane = threadIdx.x & 31, w = threadIdx.x >> 5;
    #pragma unroll
    for (int o = 16; o; o >>= 1) v = fmaxf(v, __shfl_xor_sync(0xffffffffu, v, o));
    if (lane == 0) sh[w] = v;
    __syncthreads();
    if (w == 0) {
        float x = sh[lane];
        #pragma unroll
        for (int o = 16; o; o >>= 1) x = fmaxf(x, __shfl_xor_sync(0xffffffffu, x, o));
        if (lane == 0) sh[0] = x;
    }
    __syncthreads();
    float r = sh[0];
    __syncthreads();
    return r;
}
__device__ __forceinline__ float blkSum(float v, float* sh) {
    int lane = threadIdx.x & 31, w = threadIdx.x >> 5;
    #pragma unroll
    for (int o = 16; o; o >>= 1) v += __shfl_xor_sync(0xffffffffu, v, o);
    if (lane == 0) sh[w] = v;
    __syncthreads();
    if (w == 0) {
        float x = sh[lane];
        #pragma unroll
        for (int o = 16; o; o >>= 1) x += __shfl_xor_sync(0xffffffffu, x, o);
        if (lane == 0) sh[0] = x;
    }
    __syncthreads();
    float r = sh[0];
    __syncthreads();
    return r;
}

// softmax over rowmax (4096) -> alpha; also zero q2c
__global__ void k_alphasm() {
    __shared__ float sh[32];
    int tid = threadIdx.x;
    float m = -1e30f;
    for (int i = tid; i < TC; i += 1024) m = fmaxf(m, d_rowmax[i]);
    m = blkMax(m, sh);
    float s = 0.f;
    for (int i = tid; i < TC; i += 1024) s += expf(d_rowmax[i] - m);
    s = blkSum(s, sh);
    float inv = 1.f/s;
    for (int i = tid; i < TC; i += 1024) d_alpha[i] = expf(d_rowmax[i] - m)*inv;
    if (tid < DD2) d_q2c[tid] = 0.f;
}

__global__ void k_q2c() {
    int j = blockIdx.x*256 + threadIdx.x;
    int t0 = blockIdx.y*128;
    if (j >= DD2) return;
    float s = 0.f;
    for (int t = t0; t < t0+128; ++t) s += d_alpha[t]*d_Cb[(size_t)t*DD2 + j];
    atomicAdd(&d_q2c[j], s);
}

__global__ void k_qac() {
    int i = blockIdx.x*256 + threadIdx.x;
    if (i >= TC*DD2) return;
    int t = i / DD2, j = i - t*DD2;
    float c = d_Cb[i], a = d_c2q[i];
    float* row = d_qac + (size_t)t*QACD;
    row[j]        = c;
    row[DD2 + j]  = a;
    row[2*DD2 + j]= c*a;
    row[3*DD2 + j]= c*d_q2c[j];
}

// logits[t] = qac[t].w[0:2848] + M[t].w[2848:3560]
__global__ void k_logits(const float* __restrict__ Mx, const float* __restrict__ w) {
    int t = blockIdx.x*8 + (threadIdx.x >> 5);
    int lane = threadIdx.x & 31;
    if (t >= TC) return;
    float s = 0.f;
    const float* qr = d_qac + (size_t)t*QACD;
    for (int k = lane; k < QACD; k += 32) s += qr[k]*w[k];
    const float* mr = Mx + (size_t)t*DD2;
    for (int k = lane; k < DD2; k += 32) s += mr[k]*w[QACD + k];
    #pragma unroll
    for (int off = 16; off; off >>= 1) s += __shfl_down_sync(0xffffffffu, s, off);
    if (lane == 0) d_lg[t] = s;
}

__global__ void k_smout(float* __restrict__ o) {
    __shared__ float sh[32];
    int tid = threadIdx.x;
    float m = -1e30f;
    for (int i = tid; i < TC; i += 1024) m = fmaxf(m, d_lg[i]);
    m = blkMax(m, sh);
    float s = 0.f;
    for (int i = tid; i < TC; i += 1024) s += expf(d_lg[i] - m);
    s = blkSum(s, sh);
    float inv = 1.f/s;
    for (int i = tid; i < TC; i += 1024) o[i] = expf(d_lg[i] - m)*inv;
}

// ---------------- host ----------------
static float* symaddr(const void* sym) {
    void* p = nullptr;
    cudaGetSymbolAddress(&p, sym);
    return (float*)p;
}

static void gemm(const float* A, const float* B, const float* bias, float* C,
                 int M, int N, int K)
{
    dim3 grid((N + 127)/128, (M + 127)/128);
    k_gemm_abt<<<grid, 256>>>(A, B, bias, C, M, N, K);
}

static void scan(const float* xWf, const float* xWb, const float* Whh,
                 const float* h0, float* out, int T)
{
    k_zeroflags<<<1, 128>>>();
    k_scan<<<2*NB, 1024>>>(xWf, xWb, Whh, h0, out, T);
}

extern "C" void kernel_launch(void* const* d_in, const int* in_sizes, int n_in,
                              void* d_out, int out_size)
{
    const int*   chars_ctx = (const int*)  d_in[0];
    const int*   chars_qry = (const int*)  d_in[1];
    const float* elmo_ctx  = (const float*)d_in[2];
    const float* elmo_qry  = (const float*)d_in[3];
    const float* char_emb  = (const float*)d_in[4];
    const float* conv_w    = (const float*)d_in[5];
    const float* conv_b    = (const float*)d_in[6];
    const float* hw_plain_w= (const float*)d_in[7];
    const float* hw_plain_b= (const float*)d_in[8];
    const float* hw_gate_w = (const float*)d_in[9];
    const float* hw_gate_b = (const float*)d_in[10];
    const float* ctx_Wih   = (const float*)d_in[11];
    const float* ctx_Whh   = (const float*)d_in[12];
    const float* ctx_b     = (const float*)d_in[13];
    const float* sim_w     = (const float*)d_in[14];
    const float* mod1_Wih  = (const float*)d_in[15];
    const float* mod1_Whh  = (const float*)d_in[16];
    const float* mod1_b    = (const float*)d_in[17];
    const float* mod2_Wih  = (const float*)d_in[18];
    const float* mod2_Whh  = (const float*)d_in[19];
    const float* mod2_b    = (const float*)d_in[20];
    const float* pos_Wih   = (const float*)d_in[21];
    const float* pos_Whh   = (const float*)d_in[22];
    const float* pos_b     = (const float*)d_in[23];
    const float* pos1_w    = (const float*)d_in[24];
    const float* pos2_w    = (const float*)d_in[25];
    const float* h0_ctx_c  = (const float*)d_in[26];
    const float* h0_ctx_q  = (const float*)d_in[27];
    const float* h0_mod    = (const float*)d_in[28];
    const float* h0_pos    = (const float*)d_in[29];
    float* out = (float*)d_out;

    float* x_ctx = symaddr(d_x_ctx);
    float* x_qry = symaddr(d_x_qry);
    float* t1    = symaddr(d_t1);
    float* t2    = symaddr(d_t2);
    float* xWf   = symaddr(d_xWf);
    float* xWb   = symaddr(d_xWb);
    float* Cb    = symaddr(d_Cb);
    float* Qb    = symaddr(d_Qb);
    float* Qt    = symaddr(d_Qt);
    float* CW    = symaddr(d_CW);
    float* sim   = symaddr(d_sim);
    float* cw    = symaddr(d_cw);
    float* qw    = symaddr(d_qw);
    float* c2q   = symaddr(d_c2q);
    float* qac   = symaddr(d_qac);
    float* Mb    = symaddr(d_Mb);
    float* M2b   = symaddr(d_M2b);

    // 1) char CNN + elmo concat
    k_convw<<<196, 256>>>(conv_w);
    k_charcnn<<<TC, 128>>>(chars_ctx, char_emb, conv_b, x_ctx);
    k_charcnn<<<TQ, 128>>>(chars_qry, char_emb, conv_b, x_qry);
    k_elmo<<<(TC*256 + 255)/256, 256>>>(elmo_ctx, x_ctx, TC);
    k_elmo<<<(TQ*256 + 255)/256, 256>>>(elmo_qry, x_qry, TQ);

    // 2) highway x2 (ctx and qry)
    for (int l = 0; l < 2; ++l) {
        gemm(x_ctx, hw_gate_w  + l*DHID*DHID, hw_gate_b  + l*DHID, t1, TC, DHID, DHID);
        gemm(x_ctx, hw_plain_w + l*DHID*DHID, hw_plain_b + l*DHID, t2, TC, DHID, DHID);
        k_hwy<<<(TC*DHID + 255)/256, 256>>>(x_ctx, t1, t2, TC*DHID);
        gemm(x_qry, hw_gate_w  + l*DHID*DHID, hw_gate_b  + l*DHID, t1, TQ, DHID, DHID);
        gemm(x_qry, hw_plain_w + l*DHID*DHID, hw_plain_b + l*DHID, t2, TQ, DHID, DHID);
        k_hwy<<<(TQ*DHID + 255)/256, 256>>>(x_qry, t1, t2, TQ*DHID);
    }

    // 3) context BiLSTM -> C
    gemm(x_ctx, ctx_Wih,             ctx_b,       xWf, TC, NGT, DHID);
    gemm(x_ctx, ctx_Wih + NGT*DHID,  ctx_b + NGT, xWb, TC, NGT, DHID);
    scan(xWf, xWb, ctx_Whh, h0_ctx_c, Cb, TC);

    // 4) query BiLSTM -> Q
    gemm(x_qry, ctx_Wih,             ctx_b,       xWf, TQ, NGT, DHID);
    gemm(x_qry, ctx_Wih + NGT*DHID,  ctx_b + NGT, xWb, TQ, NGT, DHID);
    scan(xWf, xWb, ctx_Whh, h0_ctx_q, Qb, TQ);

    // 5) attention
    k_rowdot<<<TC/8, 256>>>(Cb, sim_w,        cw, TC, DD2);
    k_rowdot<<<TQ/8, 256>>>(Qb, sim_w + DD2,  qw, TQ, DD2);
    k_scalecols<<<(TC*DD2 + 255)/256, 256>>>(Cb, sim_w + 2*DD2, CW, TC*DD2);
    gemm(CW, Qb, nullptr, sim, TC, TQ, DD2);      // (C*w_cq) @ Q^T
    k_simsm<<<TC/8, 256>>>();                     // + cw + qw, rowmax, softmax
    k_qt<<<(DD2*TQ + 255)/256, 256>>>();
    gemm(sim, Qt, nullptr, c2q, TC, DD2, TQ);     // attn @ Q
    k_alphasm<<<1, 1024>>>();
    { dim3 gq((DD2 + 255)/256, 32); k_q2c<<<gq, 256>>>(); }
    k_qac<<<(TC*DD2 + 255)/256, 256>>>();

    // 6) mod1 BiLSTM (input 2848) -> M
    gemm(qac, mod1_Wih,             mod1_b,       xWf, TC, NGT, QACD);
    gemm(qac, mod1_Wih + NGT*QACD,  mod1_b + NGT, xWb, TC, NGT, QACD);
    scan(xWf, xWb, mod1_Whh, h0_mod, Mb, TC);

    // 7) mod2 BiLSTM (input 712) -> M2
    gemm(Mb, mod2_Wih,            mod2_b,       xWf, TC, NGT, DD2);
    gemm(Mb, mod2_Wih + NGT*DD2,  mod2_b + NGT, xWb, TC, NGT, DD2);
    scan(xWf, xWb, mod2_Whh, h0_mod + 2*DHID, M2b, TC);

    // 8) pos1 = softmax([qac, M2] @ pos1_w)
    k_logits<<<TC/8, 256>>>(M2b, pos1_w);
    k_smout<<<1, 1024>>>(out);

    // 9) pos BiLSTM on M2 -> Mb (reuse), pos2
    gemm(M2b, pos_Wih,            pos_b,       xWf, TC, NGT, DD2);
    gemm(M2b, pos_Wih + NGT*DD2,  pos_b + NGT, xWb, TC, NGT, DD2);
    scan(xWf, xWb, pos_Whh, h0_pos, Mb, TC);
    k_logits<<<TC/8, 256>>>(Mb, pos2_w);
    k_smout<<<1, 1024>>>(out + TC);
}

// round 8
// speedup vs baseline: 5.1086x; 1.1531x over previous
#include <cuda_runtime.h>
#include <math.h>

#define TC   4096
#define TQ   128
#define DHID 356
#define DD2  712
#define NGT  1424
#define QACD 2848
#define UPB  8
#define NB   45      // ceil(356/8) blocks per direction

// ---------------- scratch (device globals; no allocation allowed) ----------------
__device__ float d_wt[5*100*100];
__device__ float d_x_ctx[TC*DHID];
__device__ float d_x_qry[TQ*DHID];
__device__ float d_t1[TC*DHID];
__device__ float d_t2[TC*DHID];
__device__ float d_xWf[TC*NGT];
__device__ float d_xWb[TC*NGT];
__device__ float d_Cb[TC*DD2];
__device__ float d_Qb[TQ*DD2];
__device__ float d_Qt[DD2*TQ];
__device__ float d_CW[TC*DD2];
__device__ float d_sim[TC*TQ];
__device__ float d_cw[TC];
__device__ float d_qw[TQ];
__device__ float d_rowmax[TC];
__device__ float d_alpha[TC];
__device__ float d_c2q[TC*DD2];
__device__ float d_q2c[DD2];
__device__ float d_qac[TC*QACD];
__device__ float d_Mb[TC*DD2];
__device__ float d_M2b[TC*DD2];
__device__ float d_lg[TC];
// Padded to one 128B line per block so pollers hit distinct LTS slices.
__device__ float g_hbuf[2][2][NB][32];   // [dir][parity][block][pad]
__device__ int   g_flags[2][NB][32];     // [dir][block][pad]

// ---------------- conv weight transpose: w[o][i][k] -> wt[k][i][o] ----------------
__global__ void k_convw(const float* __restrict__ w) {
    int idx = blockIdx.x*256 + threadIdx.x;
    if (idx < 50000) {
        int o = idx / 500; int r = idx - o*500; int i = r/5; int k = r - i*5;
        d_wt[(k*100+i)*100 + o] = w[idx];
    }
}

// ---------------- char CNN: one block per token ----------------
__global__ void k_charcnn(const int* __restrict__ chars, const float* __restrict__ emb,
                          const float* __restrict__ cb, float* __restrict__ xo)
{
    __shared__ float es[20][100];
    int t = blockIdx.x, tid = threadIdx.x;
    for (int idx = tid; idx < 2000; idx += 128) ((float*)es)[idx] = 0.f;
    __syncthreads();
    for (int idx = tid; idx < 1600; idx += 128) {
        int h = idx / 100, c = idx - h*100;
        es[h+2][c] = emb[chars[t*16+h]*100 + c];
    }
    __syncthreads();
    if (tid < 100) {
        float acc[16];
        float b = cb[tid];
        #pragma unroll
        for (int h = 0; h < 16; ++h) acc[h] = b;
        for (int i = 0; i < 100; ++i) {
            float ev[20];
            #pragma unroll
            for (int h2 = 0; h2 < 20; ++h2) ev[h2] = es[h2][i];
            #pragma unroll
            for (int k = 0; k < 5; ++k) {
                float wv = d_wt[(k*100+i)*100 + tid];
                #pragma unroll
                for (int h = 0; h < 16; ++h) acc[h] += ev[h+k]*wv;
            }
        }
        float m = acc[0];
        #pragma unroll
        for (int h = 1; h < 16; ++h) m = fmaxf(m, acc[h]);
        xo[t*DHID + tid] = m;
    }
}

// ---------------- elmo concat copy ----------------
__global__ void k_elmo(const float* __restrict__ e, float* __restrict__ xo, int T) {
    int idx = blockIdx.x*256 + threadIdx.x;
    if (idx < T*256) { int t = idx >> 8, j = idx & 255; xo[t*DHID + 100 + j] = e[idx]; }
}

// ---------------- SGEMM: C = A(MxK) * B(NxK)^T (+ bias[n]) ----------------
// 128x128 tile, BK=16, double-buffered smem, register prefetch, 1 sync/tile.
__global__ __launch_bounds__(256)
void k_gemm_abt(const float* __restrict__ A, const float* __restrict__ B,
                const float* __restrict__ bias, float* __restrict__ C,
                int M, int N, int K)
{
    __shared__ float As[2][16][132];
    __shared__ float Bs[2][16][132];
    int bm = blockIdx.y*128, bn = blockIdx.x*128;
    int tid = threadIdx.x;
    int tx = tid & 15, ty = tid >> 4;
    int l0 = tid*2, l1 = tid*2 + 1;
    int r0 = l0 >> 2, c40 = (l0 & 3)*4;
    int r1 = l1 >> 2, c41 = (l1 & 3)*4;

    float4 pa0, pa1, pb0, pb1;

#define LOADV(dst, base, row, lim, kcol)                                              \
    dst = make_float4(0.f,0.f,0.f,0.f);                                               \
    if ((row) < (lim)) {                                                              \
        if ((kcol) + 3 < K) dst = *reinterpret_cast<const float4*>((base) + (size_t)(row)*K + (kcol)); \
        else if ((kcol) < K) {                                                        \
            const float* p_ = (base) + (size_t)(row)*K;                               \
            float t0_ = p_[(kcol)];                                                   \
            float t1_ = ((kcol)+1 < K) ? p_[(kcol)+1] : 0.f;                          \
            float t2_ = ((kcol)+2 < K) ? p_[(kcol)+2] : 0.f;                          \
            float t3_ = ((kcol)+3 < K) ? p_[(kcol)+3] : 0.f;                          \
            dst = make_float4(t0_, t1_, t2_, t3_);                                    \
        }                                                                             \
    }

#define LOADTILE(kt)                                \
    LOADV(pa0, A, bm + r0, M, (kt) + c40)           \
    LOADV(pa1, A, bm + r1, M, (kt) + c41)           \
    LOADV(pb0, B, bn + r0, N, (kt) + c40)           \
    LOADV(pb1, B, bn + r1, N, (kt) + c41)

#define STORETILE(buf)                                              \
    As[buf][c40+0][r0]=pa0.x; As[buf][c40+1][r0]=pa0.y;             \
    As[buf][c40+2][r0]=pa0.z; As[buf][c40+3][r0]=pa0.w;             \
    As[buf][c41+0][r1]=pa1.x; As[buf][c41+1][r1]=pa1.y;             \
    As[buf][c41+2][r1]=pa1.z; As[buf][c41+3][r1]=pa1.w;             \
    Bs[buf][c40+0][r0]=pb0.x; Bs[buf][c40+1][r0]=pb0.y;             \
    Bs[buf][c40+2][r0]=pb0.z; Bs[buf][c40+3][r0]=pb0.w;             \
    Bs[buf][c41+0][r1]=pb1.x; Bs[buf][c41+1][r1]=pb1.y;             \
    Bs[buf][c41+2][r1]=pb1.z; Bs[buf][c41+3][r1]=pb1.w;

    float acc[8][8];
    #pragma unroll
    for (int i = 0; i < 8; ++i)
        #pragma unroll
        for (int j = 0; j < 8; ++j) acc[i][j] = 0.f;

    LOADTILE(0)
    STORETILE(0)
    __syncthreads();
    int cur = 0;
    for (int kt = 0; kt < K; kt += 16) {
        bool hasNext = (kt + 16 < K);
        if (hasNext) { LOADTILE(kt+16) }
        #pragma unroll
        for (int k = 0; k < 16; ++k) {
            float4 a0 = *reinterpret_cast<const float4*>(&As[cur][k][ty*8]);
            float4 a1 = *reinterpret_cast<const float4*>(&As[cur][k][ty*8+4]);
            float4 b0 = *reinterpret_cast<const float4*>(&Bs[cur][k][tx*8]);
            float4 b1 = *reinterpret_cast<const float4*>(&Bs[cur][k][tx*8+4]);
            float a[8] = {a0.x,a0.y,a0.z,a0.w,a1.x,a1.y,a1.z,a1.w};
            float b[8] = {b0.x,b0.y,b0.z,b0.w,b1.x,b1.y,b1.z,b1.w};
            #pragma unroll
            for (int i = 0; i < 8; ++i)
                #pragma unroll
                for (int j = 0; j < 8; ++j) acc[i][j] += a[i]*b[j];
        }
        if (hasNext) {
            STORETILE(1-cur)      // other buffer; prev-iter sync protects it
            __syncthreads();
            cur ^= 1;
        }
    }
    #pragma unroll
    for (int i = 0; i < 8; ++i) {
        int row = bm + ty*8 + i;
        if (row >= M) continue;
        #pragma unroll
        for (int j = 0; j < 8; ++j) {
            int col = bn + tx*8 + j;
            if (col < N) {
                float v = acc[i][j];
                if (bias) v += bias[col];
                C[(size_t)row*N + col] = v;
            }
        }
    }
}

// ---------------- highway combine ----------------
__global__ void k_hwy(float* __restrict__ x, const float* __restrict__ g,
                      const float* __restrict__ p, int n)
{
    int i = blockIdx.x*256 + threadIdx.x;
    if (i < n) {
        float gv = 1.f/(1.f + expf(-g[i]));
        float pv = fmaxf(p[i], 0.f);
        x[i] = gv*pv + (1.f - gv)*x[i];
    }
}

// ---------------- flag reset before each scan ----------------
__global__ void k_zeroflags() {
    int n = 2*NB*32;
    for (int i = threadIdx.x; i < n; i += 1024) ((int*)g_flags)[i] = 0;
}

// ---------------- persistent BiLSTM scan (both directions in one launch) ----------
// 45 blocks/direction, 8 units/block, 1024 threads (32 warps = 32 gate rows).
// Warp 0: activations + publish h (own padded line) + release flag (own line).
// Warps 1..31: each owns 1-2 producer blocks — spin on that flag, then fetch
// its 8 h values straight into smem (pipelines gather behind flag arrival).
// Flags/h padded to 128B lines so spinning spreads across 45 LTS lines.
__global__ __launch_bounds__(1024, 1)
void k_scan(const float* __restrict__ xWf, const float* __restrict__ xWb,
            const float* __restrict__ Whh, const float* __restrict__ h0,
            float* __restrict__ out, int T)
{
    __shared__ float ws[32][DHID];
    __shared__ float hs[DHID];
    __shared__ float zred[32];
    __shared__ float cs[UPB];
    int dir = blockIdx.x / NB;
    int blk = blockIdx.x - dir*NB;
    int tid = threadIdx.x;
    int warp = tid >> 5, lane = tid & 31;
    const float* xW = dir ? xWb : xWf;
    const float* W  = Whh + (size_t)dir*NGT*DHID;
    int u0 = blk*UPB;

    int r  = warp;                 // gate row: r = g*8 + ui
    int gg = r >> 3, ui = r & 7;
    int uu_r = u0 + ui;
    int j  = gg*DHID + uu_r;       // row in [0,1424)
    bool rowvalid = (uu_r < DHID);

    for (int idx = tid; idx < 32*DHID; idx += 1024) {
        int rr = idx / DHID, k = idx - rr*DHID;
        int g2 = rr >> 3, u2 = rr & 7;
        ws[rr][k] = (u0+u2 < DHID) ? W[(size_t)(g2*DHID + u0 + u2)*DHID + k] : 0.f;
    }
    if (tid < DHID) hs[tid] = h0[dir*DHID + tid];
    if (tid < UPB)  cs[tid] = (u0+tid < DHID) ? h0[dir*DHID + u0 + tid] : 0.f;

    float xw = 0.f;
    if (lane == 0 && rowvalid) {
        int ti0 = dir ? (T-1) : 0;
        xw = __ldg(&xW[(size_t)ti0*NGT + j]);
    }
    __syncthreads();

    for (int t = 0; t < T; ++t) {
        int ti = dir ? (T-1-t) : t;
        // --- h @ Whh^T for this warp's gate row (operands in smem) ---
        float s = 0.f;
        #pragma unroll
        for (int i = 0; i < 11; ++i) s += ws[r][lane + 32*i]*hs[lane + 32*i];
        if (lane < 4) s += ws[r][352 + lane]*hs[352 + lane];
        #pragma unroll
        for (int o = 16; o; o >>= 1) s += __shfl_down_sync(0xffffffffu, s, o);
        if (lane == 0) zred[r] = s + xw;
        __syncthreads();

        if (warp == 0) {
            float z = zred[lane];
            float a = ((lane >> 3) == 2) ? tanhf(z)
                                         : __fdividef(1.f, 1.f + __expf(-z));
            int u = lane & 7;
            float si = __shfl_sync(0xffffffffu, a, u);
            float sf = __shfl_sync(0xffffffffu, a, 8 + u);
            float tg = __shfl_sync(0xffffffffu, a, 16 + u);
            float so = __shfl_sync(0xffffffffu, a, 24 + u);
            int uu = u0 + lane;
            float h = 0.f;
            bool act = (lane < UPB) && (uu < DHID);
            if (act) {
                float c = sf*cs[lane] + si*tg;
                h = so*tanhf(c);
                cs[lane] = c;
                ((volatile float*)&g_hbuf[dir][t & 1][blk][0])[lane] = h;
            }
            __threadfence();                 // h visible at GPU scope...
            __syncwarp(0xffffffffu);
            if (lane == 0)
                *(volatile int*)&g_flags[dir][blk][0] = t + 1;   // release
            if (act) out[(size_t)ti*DD2 + dir*DHID + uu] = h;    // off crit path
        }
        // prefetch next step's xW
        if (lane == 0 && rowvalid && t + 1 < T) {
            int tn = dir ? (T-2-t) : (t+1);
            xw = __ldg(&xW[(size_t)tn*NGT + j]);
        }
        // warps 1..31: per-block poll + immediate h gather
        if (warp >= 1 && t + 1 < T) {
            int tgt = t + 1;
            #pragma unroll
            for (int pass = 0; pass < 2; ++pass) {
                int b = (warp - 1) + pass*31;
                if (b < NB) {
                    volatile int* fp = &g_flags[dir][b][0];
                    while (*fp < tgt) { }
                    int u = b*UPB + lane;
                    if (lane < UPB && u < DHID)
                        hs[u] = ((volatile float*)&g_hbuf[dir][t & 1][b][0])[lane];
                }
            }
        }
        __syncthreads();
    }
}

// ---------------- row dot (gemv): o[t] = X[t,:K] . w ----------------
__global__ void k_rowdot(const float* __restrict__ X, const float* __restrict__ w,
                         float* __restrict__ o, int T, int K)
{
    int t = blockIdx.x*8 + (threadIdx.x >> 5);
    int lane = threadIdx.x & 31;
    if (t >= T) return;
    float s = 0.f;
    for (int k = lane; k < K; k += 32) s += X[(size_t)t*K + k]*w[k];
    #pragma unroll
    for (int off = 16; off; off >>= 1) s += __shfl_down_sync(0xffffffffu, s, off);
    if (lane == 0) o[t] = s;
}

__global__ void k_scalecols(const float* __restrict__ C, const float* __restrict__ w,
                            float* __restrict__ o, int n)
{
    int i = blockIdx.x*256 + threadIdx.x;
    if (i < n) o[i] = C[i]*w[i % DD2];
}

__global__ void k_qt() {
    int i = blockIdx.x*256 + threadIdx.x;
    if (i < DD2*TQ) { int j = i / TQ, q = i - j*TQ; d_Qt[i] = d_Qb[q*DD2 + j]; }
}

// sim[t][q] += cw[t]+qw[q]; rowmax; row softmax in-place
__global__ void k_simsm() {
    int t = blockIdx.x*8 + (threadIdx.x >> 5);
    int lane = threadIdx.x & 31;
    if (t >= TC) return;
    float cw = d_cw[t];
    float v[4];
    float m = -1e30f;
    #pragma unroll
    for (int i = 0; i < 4; ++i) {
        int q = lane + 32*i;
        v[i] = d_sim[t*TQ + q] + cw + d_qw[q];
        m = fmaxf(m, v[i]);
    }
    #pragma unroll
    for (int off = 16; off; off >>= 1) m = fmaxf(m, __shfl_xor_sync(0xffffffffu, m, off));
    float s = 0.f;
    #pragma unroll
    for (int i = 0; i < 4; ++i) { v[i] = expf(v[i]-m); s += v[i]; }
    #pragma unroll
    for (int off = 16; off; off >>= 1) s += __shfl_xor_sync(0xffffffffu, s, off);
    float inv = 1.f/s;
    #pragma unroll
    for (int i = 0; i < 4; ++i) d_sim[t*TQ + lane + 32*i] = v[i]*inv;
    if (lane == 0) d_rowmax[t] = m;
}

__device__ __forceinline__ float blkMax(float v, float* sh) {
    int lane = threadIdx.x & 31, w = threadIdx.x >> 5;
    #pragma unroll
    for (int o = 16; o; o >>= 1) v = fmaxf(v, __shfl_xor_sync(0xffffffffu, v, o));
    if (lane == 0) sh[w] = v;
    __syncthreads();
    if (w == 0) {
        float x = sh[lane];
        #pragma unroll
        for (int o = 16; o; o >>= 1) x = fmaxf(x, __shfl_xor_sync(0xffffffffu, x, o));
        if (lane == 0) sh[0] = x;
    }
    __syncthreads();
    float r = sh[0];
    __syncthreads();
    return r;
}
__device__ __forceinline__ float blkSum(float v, float* sh) {
    int lane = threadIdx.x & 31, w = threadIdx.x >> 5;
    #pragma unroll
    for (int o = 16; o; o >>= 1) v += __shfl_xor_sync(0xffffffffu, v, o);
    if (lane == 0) sh[w] = v;
    __syncthreads();
    if (w == 0) {
        float x = sh[lane];
        #pragma unroll
        for (int o = 16; o; o >>= 1) x += __shfl_xor_sync(0xffffffffu, x, o);
        if (lane == 0) sh[0] = x;
    }
    __syncthreads();
    float r = sh[0];
    __syncthreads();
    return r;
}

// softmax over rowmax (4096) -> alpha; also zero q2c
__global__ void k_alphasm() {
    __shared__ float sh[32];
    int tid = threadIdx.x;
    float m = -1e30f;
    for (int i = tid; i < TC; i += 1024) m = fmaxf(m, d_rowmax[i]);
    m = blkMax(m, sh);
    float s = 0.f;
    for (int i = tid; i < TC; i += 1024) s += expf(d_rowmax[i] - m);
    s = blkSum(s, sh);
    float inv = 1.f/s;
    for (int i = tid; i < TC; i += 1024) d_alpha[i] = expf(d_rowmax[i] - m)*inv;
    if (tid < DD2) d_q2c[tid] = 0.f;
}

__global__ void k_q2c() {
    int j = blockIdx.x*256 + threadIdx.x;
    int t0 = blockIdx.y*128;
    if (j >= DD2) return;
    float s = 0.f;
    for (int t = t0; t < t0+128; ++t) s += d_alpha[t]*d_Cb[(size_t)t*DD2 + j];
    atomicAdd(&d_q2c[j], s);
}

__global__ void k_qac() {
    int i = blockIdx.x*256 + threadIdx.x;
    if (i >= TC*DD2) return;
    int t = i / DD2, j = i - t*DD2;
    float c = d_Cb[i], a = d_c2q[i];
    float* row = d_qac + (size_t)t*QACD;
    row[j]        = c;
    row[DD2 + j]  = a;
    row[2*DD2 + j]= c*a;
    row[3*DD2 + j]= c*d_q2c[j];
}

// logits[t] = qac[t].w[0:2848] + M[t].w[2848:3560]
__global__ void k_logits(const float* __restrict__ Mx, const float* __restrict__ w) {
    int t = blockIdx.x*8 + (threadIdx.x >> 5);
    int lane = threadIdx.x & 31;
    if (t >= TC) return;
    float s = 0.f;
    const float* qr = d_qac + (size_t)t*QACD;
    for (int k = lane; k < QACD; k += 32) s += qr[k]*w[k];
    const float* mr = Mx + (size_t)t*DD2;
    for (int k = lane; k < DD2; k += 32) s += mr[k]*w[QACD + k];
    #pragma unroll
    for (int off = 16; off; off >>= 1) s += __shfl_down_sync(0xffffffffu, s, off);
    if (lane == 0) d_lg[t] = s;
}

__global__ void k_smout(float* __restrict__ o) {
    __shared__ float sh[32];
    int tid = threadIdx.x;
    float m = -1e30f;
    for (int i = tid; i < TC; i += 1024) m = fmaxf(m, d_lg[i]);
    m = blkMax(m, sh);
    float s = 0.f;
    for (int i = tid; i < TC; i += 1024) s += expf(d_lg[i] - m);
    s = blkSum(s, sh);
    float inv = 1.f/s;
    for (int i = tid; i < TC; i += 1024) o[i] = expf(d_lg[i] - m)*inv;
}

// ---------------- host ----------------
static float* symaddr(const void* sym) {
    void* p = nullptr;
    cudaGetSymbolAddress(&p, sym);
    return (float*)p;
}

static void gemm(const float* A, const float* B, const float* bias, float* C,
                 int M, int N, int K)
{
    dim3 grid((N + 127)/128, (M + 127)/128);
    k_gemm_abt<<<grid, 256>>>(A, B, bias, C, M, N, K);
}

static void scan(const float* xWf, const float* xWb, const float* Whh,
                 const float* h0, float* out, int T)
{
    k_zeroflags<<<1, 1024>>>();
    k_scan<<<2*NB, 1024>>>(xWf, xWb, Whh, h0, out, T);
}

extern "C" void kernel_launch(void* const* d_in, const int* in_sizes, int n_in,
                              void* d_out, int out_size)
{
    const int*   chars_ctx = (const int*)  d_in[0];
    const int*   chars_qry = (const int*)  d_in[1];
    const float* elmo_ctx  = (const float*)d_in[2];
    const float* elmo_qry  = (const float*)d_in[3];
    const float* char_emb  = (const float*)d_in[4];
    const float* conv_w    = (const float*)d_in[5];
    const float* conv_b    = (const float*)d_in[6];
    const float* hw_plain_w= (const float*)d_in[7];
    const float* hw_plain_b= (const float*)d_in[8];
    const float* hw_gate_w = (const float*)d_in[9];
    const float* hw_gate_b = (const float*)d_in[10];
    const float* ctx_Wih   = (const float*)d_in[11];
    const float* ctx_Whh   = (const float*)d_in[12];
    const float* ctx_b     = (const float*)d_in[13];
    const float* sim_w     = (const float*)d_in[14];
    const float* mod1_Wih  = (const float*)d_in[15];
    const float* mod1_Whh  = (const float*)d_in[16];
    const float* mod1_b    = (const float*)d_in[17];
    const float* mod2_Wih  = (const float*)d_in[18];
    const float* mod2_Whh  = (const float*)d_in[19];
    const float* mod2_b    = (const float*)d_in[20];
    const float* pos_Wih   = (const float*)d_in[21];
    const float* pos_Whh   = (const float*)d_in[22];
    const float* pos_b     = (const float*)d_in[23];
    const float* pos1_w    = (const float*)d_in[24];
    const float* pos2_w    = (const float*)d_in[25];
    const float* h0_ctx_c  = (const float*)d_in[26];
    const float* h0_ctx_q  = (const float*)d_in[27];
    const float* h0_mod    = (const float*)d_in[28];
    const float* h0_pos    = (const float*)d_in[29];
    float* out = (float*)d_out;

    float* x_ctx = symaddr(d_x_ctx);
    float* x_qry = symaddr(d_x_qry);
    float* t1    = symaddr(d_t1);
    float* t2    = symaddr(d_t2);
    float* xWf   = symaddr(d_xWf);
    float* xWb   = symaddr(d_xWb);
    float* Cb    = symaddr(d_Cb);
    float* Qb    = symaddr(d_Qb);
    float* Qt    = symaddr(d_Qt);
    float* CW    = symaddr(d_CW);
    float* sim   = symaddr(d_sim);
    float* cw    = symaddr(d_cw);
    float* qw    = symaddr(d_qw);
    float* c2q   = symaddr(d_c2q);
    float* qac   = symaddr(d_qac);
    float* Mb    = symaddr(d_Mb);
    float* M2b   = symaddr(d_M2b);

    // 1) char CNN + elmo concat
    k_convw<<<196, 256>>>(conv_w);
    k_charcnn<<<TC, 128>>>(chars_ctx, char_emb, conv_b, x_ctx);
    k_charcnn<<<TQ, 128>>>(chars_qry, char_emb, conv_b, x_qry);
    k_elmo<<<(TC*256 + 255)/256, 256>>>(elmo_ctx, x_ctx, TC);
    k_elmo<<<(TQ*256 + 255)/256, 256>>>(elmo_qry, x_qry, TQ);

    // 2) highway x2 (ctx and qry)
    for (int l = 0; l < 2; ++l) {
        gemm(x_ctx, hw_gate_w  + l*DHID*DHID, hw_gate_b  + l*DHID, t1, TC, DHID, DHID);
        gemm(x_ctx, hw_plain_w + l*DHID*DHID, hw_plain_b + l*DHID, t2, TC, DHID, DHID);
        k_hwy<<<(TC*DHID + 255)/256, 256>>>(x_ctx, t1, t2, TC*DHID);
        gemm(x_qry, hw_gate_w  + l*DHID*DHID, hw_gate_b  + l*DHID, t1, TQ, DHID, DHID);
        gemm(x_qry, hw_plain_w + l*DHID*DHID, hw_plain_b + l*DHID, t2, TQ, DHID, DHID);
        k_hwy<<<(TQ*DHID + 255)/256, 256>>>(x_qry, t1, t2, TQ*DHID);
    }

    // 3) context BiLSTM -> C
    gemm(x_ctx, ctx_Wih,             ctx_b,       xWf, TC, NGT, DHID);
    gemm(x_ctx, ctx_Wih + NGT*DHID,  ctx_b + NGT, xWb, TC, NGT, DHID);
    scan(xWf, xWb, ctx_Whh, h0_ctx_c, Cb, TC);

    // 4) query BiLSTM -> Q
    gemm(x_qry, ctx_Wih,             ctx_b,       xWf, TQ, NGT, DHID);
    gemm(x_qry, ctx_Wih + NGT*DHID,  ctx_b + NGT, xWb, TQ, NGT, DHID);
    scan(xWf, xWb, ctx_Whh, h0_ctx_q, Qb, TQ);

    // 5) attention
    k_rowdot<<<TC/8, 256>>>(Cb, sim_w,        cw, TC, DD2);
    k_rowdot<<<TQ/8, 256>>>(Qb, sim_w + DD2,  qw, TQ, DD2);
    k_scalecols<<<(TC*DD2 + 255)/256, 256>>>(Cb, sim_w + 2*DD2, CW, TC*DD2);
    gemm(CW, Qb, nullptr, sim, TC, TQ, DD2);      // (C*w_cq) @ Q^T
    k_simsm<<<TC/8, 256>>>();                     // + cw + qw, rowmax, softmax
    k_qt<<<(DD2*TQ + 255)/256, 256>>>();
    gemm(sim, Qt, nullptr, c2q, TC, DD2, TQ);     // attn @ Q
    k_alphasm<<<1, 1024>>>();
    { dim3 gq((DD2 + 255)/256, 32); k_q2c<<<gq, 256>>>(); }
    k_qac<<<(TC*DD2 + 255)/256, 256>>>();

    // 6) mod1 BiLSTM (input 2848) -> M
    gemm(qac, mod1_Wih,             mod1_b,       xWf, TC, NGT, QACD);
    gemm(qac, mod1_Wih + NGT*QACD,  mod1_b + NGT, xWb, TC, NGT, QACD);
    scan(xWf, xWb, mod1_Whh, h0_mod, Mb, TC);

    // 7) mod2 BiLSTM (input 712) -> M2
    gemm(Mb, mod2_Wih,            mod2_b,       xWf, TC, NGT, DD2);
    gemm(Mb, mod2_Wih + NGT*DD2,  mod2_b + NGT, xWb, TC, NGT, DD2);
    scan(xWf, xWb, mod2_Whh, h0_mod + 2*DHID, M2b, TC);

    // 8) pos1 = softmax([qac, M2] @ pos1_w)
    k_logits<<<TC/8, 256>>>(M2b, pos1_w);
    k_smout<<<1, 1024>>>(out);

    // 9) pos BiLSTM on M2 -> Mb (reuse), pos2
    gemm(M2b, pos_Wih,            pos_b,       xWf, TC, NGT, DD2);
    gemm(M2b, pos_Wih + NGT*DD2,  pos_b + NGT, xWb, TC, NGT, DD2);
    scan(xWf, xWb, pos_Whh, h0_pos, Mb, TC);
    k_logits<<<TC/8, 256>>>(Mb, pos2_w);
    k_smout<<<1, 1024>>>(out + TC);
}